// round 9
// baseline (speedup 1.0000x reference)
#include <cuda_runtime.h>
#include <cuda_bf16.h>
#include <cstdint>
#include <math.h>

#define NTOK 3136
#define NPAD 3200          // 25 * 128, also 50 * 64
#define CDIM 256
#define NHEAD 8
#define DFFN 1024
#define NLAYER 4
#define TOPKK 16
#define HW 56

__device__ float g_c1[128 * NTOK];
__device__ float g_gp[NHEAD * NTOK];
__device__ float g_x[NPAD * CDIM];
__device__ float g_sq[NPAD];
__device__ float g_d2[(size_t)NPAD * NPAD];
__device__ int   g_near[NTOK];
__device__ int   g_maxnear[1];
__device__ float g_qkin[NPAD * CDIM];
__device__ float g_q[NPAD * CDIM];
__device__ float g_k[NPAD * CDIM];
__device__ float g_v[NPAD * CDIM];
__device__ float g_att[NPAD * CDIM];
__device__ float g_ffh[(size_t)NPAD * DFFN];
__device__ float g_y[NPAD * CDIM];

// FMA-pipe exp (x <= ~0 usage), rel err ~2e-6
__device__ __forceinline__ float fexp(float x) {
    x = fmaxf(x, -87.0f);
    float y = x * 1.44269504088896341f;
    float r = rintf(y);
    float f = y - r;
    float p = 1.33335581e-3f;
    p = fmaf(p, f, 9.61812911e-3f);
    p = fmaf(p, f, 5.55041087e-2f);
    p = fmaf(p, f, 2.40226507e-1f);
    p = fmaf(p, f, 6.93147181e-1f);
    p = fmaf(p, f, 1.0f);
    return __int_as_float(__float_as_int(p) + (((int)r) << 23));
}

__device__ __forceinline__ unsigned f2tf32(float v) {
    unsigned r;
    asm("cvt.rna.tf32.f32 %0, %1;" : "=r"(r) : "f"(v));
    return r;
}

__device__ __forceinline__ void mma_tf32(float c[4],
    unsigned a0, unsigned a1, unsigned a2, unsigned a3,
    unsigned b0, unsigned b1)
{
    asm volatile(
        "mma.sync.aligned.m16n8k8.row.col.f32.tf32.tf32.f32 "
        "{%0,%1,%2,%3}, {%4,%5,%6,%7}, {%8,%9}, {%0,%1,%2,%3};\n"
        : "+f"(c[0]), "+f"(c[1]), "+f"(c[2]), "+f"(c[3])
        : "r"(a0), "r"(a1), "r"(a2), "r"(a3), "r"(b0), "r"(b1));
}

// zero the pad rows of x and sq (idempotent, every launch)
__global__ void pad_kernel(float* __restrict__ x, float* __restrict__ sqv) {
    int i = blockIdx.x * 256 + threadIdx.x;   // 64 blocks -> 16384 threads
    x[NTOK * CDIM + i] = 0.f;
    if (i < NPAD - NTOK) sqv[NTOK + i] = 0.f;
}

__global__ void transpose_kernel(const float* __restrict__ src, float* __restrict__ dst) {
    __shared__ float tile[32][33];
    int t0 = blockIdx.x * 32, c0 = blockIdx.y * 32;
    int tx = threadIdx.x, ty = threadIdx.y;
    tile[ty][tx] = src[(c0 + ty) * NTOK + t0 + tx];
    __syncthreads();
    dst[(t0 + ty) * CDIM + c0 + tx] = tile[tx][ty];
}

__global__ __launch_bounds__(64) void conv1_kernel(
    const float* __restrict__ src, const float* __restrict__ wt,
    const float* __restrict__ bias, float* __restrict__ out)
{
    __shared__ float ws[4 * 2304];
    int cog = blockIdx.x;
    int p = blockIdx.y * 64 + threadIdx.x;
    for (int i = threadIdx.x; i < 4 * 2304; i += 64) ws[i] = wt[cog * 4 * 2304 + i];
    __syncthreads();
    int y = p / HW, x = p % HW;
    // 8 independent chains: 4 output channels x 2 ci-parity
    float a[4][2];
    #pragma unroll
    for (int j = 0; j < 4; j++) { a[j][0] = 0.f; a[j][1] = 0.f; }
    for (int ci = 0; ci < 256; ci += 2) {
        #pragma unroll
        for (int par = 0; par < 2; par++) {
            const float* ip = src + (ci + par) * NTOK;
            const float* wp = ws + (ci + par) * 9;
            #pragma unroll
            for (int dy = 0; dy < 3; dy++) {
                int yy = y + dy - 1; if ((unsigned)yy >= HW) continue;
                #pragma unroll
                for (int dx = 0; dx < 3; dx++) {
                    int xx = x + dx - 1; if ((unsigned)xx >= HW) continue;
                    float v = ip[yy * HW + xx]; int wi = dy * 3 + dx;
                    a[0][par] = fmaf(v, wp[wi],          a[0][par]);
                    a[1][par] = fmaf(v, wp[2304 + wi],   a[1][par]);
                    a[2][par] = fmaf(v, wp[4608 + wi],   a[2][par]);
                    a[3][par] = fmaf(v, wp[6912 + wi],   a[3][par]);
                }
            }
        }
    }
    #pragma unroll
    for (int j = 0; j < 4; j++)
        out[(cog*4+j)*NTOK + p] = fmaxf(a[j][0] + a[j][1] + bias[cog*4+j], 0.f);
}

__global__ __launch_bounds__(64) void conv2_kernel(
    const float* __restrict__ c1, const float* __restrict__ wt,
    const float* __restrict__ bias, float* __restrict__ gp)
{
    __shared__ float ws[1152];
    int co = blockIdx.x;
    int p = blockIdx.y * 64 + threadIdx.x;
    for (int i = threadIdx.x; i < 1152; i += 64) ws[i] = wt[co * 1152 + i];
    __syncthreads();
    int y = p / HW, x = p % HW;
    // 4 independent accumulator chains over ci
    float a0 = 0.f, a1 = 0.f, a2 = 0.f, a3 = 0.f;
    for (int ci = 0; ci < 128; ci += 4) {
        #pragma unroll
        for (int dy = 0; dy < 3; dy++) {
            int yy = y + dy - 1; if ((unsigned)yy >= HW) continue;
            #pragma unroll
            for (int dx = 0; dx < 3; dx++) {
                int xx = x + dx - 1; if ((unsigned)xx >= HW) continue;
                int po = yy * HW + xx, wi = dy * 3 + dx;
                a0 = fmaf(c1[(ci+0) * NTOK + po], ws[(ci+0) * 9 + wi], a0);
                a1 = fmaf(c1[(ci+1) * NTOK + po], ws[(ci+1) * 9 + wi], a1);
                a2 = fmaf(c1[(ci+2) * NTOK + po], ws[(ci+2) * 9 + wi], a2);
                a3 = fmaf(c1[(ci+3) * NTOK + po], ws[(ci+3) * 9 + wi], a3);
            }
        }
    }
    float a = bias[co] + ((a0 + a1) + (a2 + a3));
    gp[co * NTOK + p] = 1.0f / (1.0f + __expf(-a));
}

__global__ __launch_bounds__(256) void sq_kernel(const float* __restrict__ x,
                                                 float* __restrict__ sq)
{
    int row = blockIdx.x * 8 + (threadIdx.x >> 5);
    int lane = threadIdx.x & 31;
    const float* r = x + row * CDIM;
    float s = 0.f;
    #pragma unroll
    for (int i = 0; i < 8; i++) { float v = r[lane + i * 32]; s = fmaf(v, v, s); }
    #pragma unroll
    for (int o = 16; o; o >>= 1) s += __shfl_xor_sync(0xffffffffu, s, o);
    if (lane == 0) sq[row] = s;
}

// -----------------------------------------------------------------------------
// d2 = sq_i + sq_j - 2 * X X^T  via tf32 mma.sync (single-pass: feeds topk only)
// -----------------------------------------------------------------------------
__global__ __launch_bounds__(256) void d2_tf32_kernel(
    const float* __restrict__ X, const float* __restrict__ sqv,
    float* __restrict__ C)
{
    __shared__ float As[128 * 36];
    __shared__ float Bs[128 * 36];
    const int tid = threadIdx.x;
    const int wid = tid >> 5, lane = tid & 31;
    const int warpM = wid >> 2, warpN = wid & 3;
    const int i0 = blockIdx.x * 128, j0 = blockIdx.y * 128;
    const int gid = lane >> 2, qid = lane & 3;

    float acc[4][4][4];
    #pragma unroll
    for (int a = 0; a < 4; a++)
        #pragma unroll
        for (int b = 0; b < 4; b++)
            #pragma unroll
            for (int c = 0; c < 4; c++) acc[a][b][c] = 0.f;

    const int lrow = tid >> 1;
    const int lk = (tid & 1) * 16;
    const float* Ag = X + (size_t)(i0 + lrow) * CDIM + lk;
    const float* Bg = X + (size_t)(j0 + lrow) * CDIM + lk;
    float* Asw = As + lrow * 36 + lk;
    float* Bsw = Bs + lrow * 36 + lk;

    for (int k0 = 0; k0 < CDIM; k0 += 32) {
        __syncthreads();
        #pragma unroll
        for (int q = 0; q < 4; q++) {
            float4 av = *(const float4*)(Ag + k0 + q * 4);
            float4 bv = *(const float4*)(Bg + k0 + q * 4);
            float4 at, bt;
            at.x = __uint_as_float(f2tf32(av.x)); at.y = __uint_as_float(f2tf32(av.y));
            at.z = __uint_as_float(f2tf32(av.z)); at.w = __uint_as_float(f2tf32(av.w));
            bt.x = __uint_as_float(f2tf32(bv.x)); bt.y = __uint_as_float(f2tf32(bv.y));
            bt.z = __uint_as_float(f2tf32(bv.z)); bt.w = __uint_as_float(f2tf32(bv.w));
            *(float4*)&Asw[q * 4] = at;
            *(float4*)&Bsw[q * 4] = bt;
        }
        __syncthreads();
        #pragma unroll
        for (int k8 = 0; k8 < 4; k8++) {
            unsigned af[4][4], bf[4][2];
            #pragma unroll
            for (int tm = 0; tm < 4; tm++) {
                const float* p = As + (warpM * 64 + tm * 16 + gid) * 36 + k8 * 8 + qid;
                af[tm][0] = __float_as_uint(p[0]);
                af[tm][1] = __float_as_uint(p[8 * 36]);
                af[tm][2] = __float_as_uint(p[4]);
                af[tm][3] = __float_as_uint(p[8 * 36 + 4]);
            }
            #pragma unroll
            for (int tn = 0; tn < 4; tn++) {
                const float* p = Bs + (warpN * 32 + tn * 8 + gid) * 36 + k8 * 8 + qid;
                bf[tn][0] = __float_as_uint(p[0]);
                bf[tn][1] = __float_as_uint(p[4]);
            }
            #pragma unroll
            for (int tm = 0; tm < 4; tm++)
                #pragma unroll
                for (int tn = 0; tn < 4; tn++)
                    mma_tf32(acc[tm][tn], af[tm][0], af[tm][1], af[tm][2], af[tm][3],
                             bf[tn][0], bf[tn][1]);
        }
    }

    #pragma unroll
    for (int tm = 0; tm < 4; tm++) {
        const int r0 = i0 + warpM * 64 + tm * 16 + gid;
        const float sr0 = sqv[r0], sr1 = sqv[r0 + 8];
        #pragma unroll
        for (int tn = 0; tn < 4; tn++) {
            const int c0i = j0 + warpN * 32 + tn * 8 + qid * 2;
            const float sc0 = sqv[c0i], sc1 = sqv[c0i + 1];
            float2 v0, v1;
            v0.x = sr0 + sc0 - 2.f * acc[tm][tn][0];
            v0.y = sr0 + sc1 - 2.f * acc[tm][tn][1];
            v1.x = sr1 + sc0 - 2.f * acc[tm][tn][2];
            v1.y = sr1 + sc1 - 2.f * acc[tm][tn][3];
            *(float2*)&C[(size_t)r0 * NPAD + c0i] = v0;
            *(float2*)&C[(size_t)(r0 + 8) * NPAD + c0i] = v1;
        }
    }
}

// -----------------------------------------------------------------------------
// 3xTF32 GEMM (fp32-accurate): C[i][j] = dot(A[i,:],B[j,:]) + bias[j] (EPI1: relu)
// hi/lo split: a*b ~= ah*bh + ah*bl + al*bh. Tile 64x64, 4 warps (2Mx2N),
// warp tile 32x32 = 2 m16-tiles x 4 n8-tiles, K chunk 32.
// -----------------------------------------------------------------------------
template<int EPI>
__global__ __launch_bounds__(128) void mma3_gemm(
    const float* __restrict__ A, const float* __restrict__ B,
    const float* __restrict__ bias, float* __restrict__ C,
    int Nn, int K)
{
    __shared__ float Ah[64 * 36], Al[64 * 36], Bh[64 * 36], Bl[64 * 36];
    const int tid = threadIdx.x;
    const int wid = tid >> 5, lane = tid & 31;
    const int warpM = wid >> 1, warpN = wid & 1;
    const int i0 = blockIdx.x * 64, j0 = blockIdx.y * 64;
    const int gid = lane >> 2, qid = lane & 3;

    float acc[2][4][4];
    #pragma unroll
    for (int a = 0; a < 2; a++)
        #pragma unroll
        for (int b = 0; b < 4; b++)
            #pragma unroll
            for (int c = 0; c < 4; c++) acc[a][b][c] = 0.f;

    const int lrow = tid >> 1;          // 0..63
    const int lk = (tid & 1) * 16;
    const float* Ag = A + (size_t)(i0 + lrow) * K + lk;
    const float* Bg = B + (size_t)(j0 + lrow) * K + lk;
    const int sbase = lrow * 36 + lk;

    for (int k0 = 0; k0 < K; k0 += 32) {
        __syncthreads();
        #pragma unroll
        for (int q = 0; q < 4; q++) {
            float4 av = *(const float4*)(Ag + k0 + q * 4);
            float4 bv = *(const float4*)(Bg + k0 + q * 4);
            float4 avh, avl, bvh, bvl;
            avh.x = __uint_as_float(f2tf32(av.x)); avl.x = __uint_as_float(f2tf32(av.x - avh.x));
            avh.y = __uint_as_float(f2tf32(av.y)); avl.y = __uint_as_float(f2tf32(av.y - avh.y));
            avh.z = __uint_as_float(f2tf32(av.z)); avl.z = __uint_as_float(f2tf32(av.z - avh.z));
            avh.w = __uint_as_float(f2tf32(av.w)); avl.w = __uint_as_float(f2tf32(av.w - avh.w));
            bvh.x = __uint_as_float(f2tf32(bv.x)); bvl.x = __uint_as_float(f2tf32(bv.x - bvh.x));
            bvh.y = __uint_as_float(f2tf32(bv.y)); bvl.y = __uint_as_float(f2tf32(bv.y - bvh.y));
            bvh.z = __uint_as_float(f2tf32(bv.z)); bvl.z = __uint_as_float(f2tf32(bv.z - bvh.z));
            bvh.w = __uint_as_float(f2tf32(bv.w)); bvl.w = __uint_as_float(f2tf32(bv.w - bvh.w));
            *(float4*)&Ah[sbase + q * 4] = avh;
            *(float4*)&Al[sbase + q * 4] = avl;
            *(float4*)&Bh[sbase + q * 4] = bvh;
            *(float4*)&Bl[sbase + q * 4] = bvl;
        }
        __syncthreads();
        #pragma unroll
        for (int k8 = 0; k8 < 4; k8++) {
            unsigned afh[2][4], afl[2][4], bfh[4][2], bfl[4][2];
            #pragma unroll
            for (int tm = 0; tm < 2; tm++) {
                const int off = (warpM * 32 + tm * 16 + gid) * 36 + k8 * 8 + qid;
                afh[tm][0] = __float_as_uint(Ah[off]);
                afh[tm][1] = __float_as_uint(Ah[off + 8 * 36]);
                afh[tm][2] = __float_as_uint(Ah[off + 4]);
                afh[tm][3] = __float_as_uint(Ah[off + 8 * 36 + 4]);
                afl[tm][0] = __float_as_uint(Al[off]);
                afl[tm][1] = __float_as_uint(Al[off + 8 * 36]);
                afl[tm][2] = __float_as_uint(Al[off + 4]);
                afl[tm][3] = __float_as_uint(Al[off + 8 * 36 + 4]);
            }
            #pragma unroll
            for (int tn = 0; tn < 4; tn++) {
                const int off = (warpN * 32 + tn * 8 + gid) * 36 + k8 * 8 + qid;
                bfh[tn][0] = __float_as_uint(Bh[off]);
                bfh[tn][1] = __float_as_uint(Bh[off + 4]);
                bfl[tn][0] = __float_as_uint(Bl[off]);
                bfl[tn][1] = __float_as_uint(Bl[off + 4]);
            }
            #pragma unroll
            for (int tm = 0; tm < 2; tm++)
                #pragma unroll
                for (int tn = 0; tn < 4; tn++) {
                    mma_tf32(acc[tm][tn], afh[tm][0], afh[tm][1], afh[tm][2], afh[tm][3],
                             bfh[tn][0], bfh[tn][1]);
                    mma_tf32(acc[tm][tn], afh[tm][0], afh[tm][1], afh[tm][2], afh[tm][3],
                             bfl[tn][0], bfl[tn][1]);
                    mma_tf32(acc[tm][tn], afl[tm][0], afl[tm][1], afl[tm][2], afl[tm][3],
                             bfh[tn][0], bfh[tn][1]);
                }
        }
    }

    #pragma unroll
    for (int tm = 0; tm < 2; tm++) {
        const int r0 = i0 + warpM * 32 + tm * 16 + gid;
        #pragma unroll
        for (int tn = 0; tn < 4; tn++) {
            const int c0i = j0 + warpN * 32 + tn * 8 + qid * 2;
            const float b0 = bias[c0i], b1 = bias[c0i + 1];
            float2 v0, v1;
            v0.x = acc[tm][tn][0] + b0; v0.y = acc[tm][tn][1] + b1;
            v1.x = acc[tm][tn][2] + b0; v1.y = acc[tm][tn][3] + b1;
            if (EPI == 1) {
                v0.x = fmaxf(v0.x, 0.f); v0.y = fmaxf(v0.y, 0.f);
                v1.x = fmaxf(v1.x, 0.f); v1.y = fmaxf(v1.y, 0.f);
            }
            *(float2*)&C[(size_t)r0 * Nn + c0i] = v0;
            *(float2*)&C[(size_t)(r0 + 8) * Nn + c0i] = v1;
        }
    }
}

__global__ void zero_kernel(int* __restrict__ nearp, int* __restrict__ maxn) {
    int i = blockIdx.x * 256 + threadIdx.x;
    if (i < NTOK) nearp[i] = 0;
    if (i == 0) *maxn = 0;
}

// top-16 smallest per row (tie: smallest index == XLA top_k), accumulate in-degree
__global__ __launch_bounds__(256) void topk_kernel(const float* __restrict__ d2,
                                                   int* __restrict__ nearp)
{
    __shared__ float vals[NTOK];
    __shared__ float rv[256];
    __shared__ int   ri[256];
    int row = blockIdx.x, tid = threadIdx.x;
    const float* rp = d2 + (size_t)row * NPAD;
    for (int i = tid; i < NTOK; i += 256) vals[i] = rp[i];
    __syncthreads();
    for (int it = 0; it < TOPKK; it++) {
        float bv = 3.0e38f; int bi = 0x7FFFFFFF;
        for (int i = tid; i < NTOK; i += 256) {
            float v = vals[i];
            if (v < bv) { bv = v; bi = i; }
        }
        rv[tid] = bv; ri[tid] = bi;
        __syncthreads();
        for (int s = 128; s > 0; s >>= 1) {
            if (tid < s) {
                float ov = rv[tid+s]; int oi = ri[tid+s];
                if (ov < rv[tid] || (ov == rv[tid] && oi < ri[tid])) { rv[tid]=ov; ri[tid]=oi; }
            }
            __syncthreads();
        }
        if (tid == 0) { atomicAdd(&nearp[ri[0]], 1); vals[ri[0]] = 3.0e38f; }
        __syncthreads();
    }
}

__global__ __launch_bounds__(256) void maxnear_kernel(const int* __restrict__ nearp,
                                                      int* __restrict__ out)
{
    __shared__ int sm[256];
    int tid = threadIdx.x;
    int m = 0;
    for (int i = tid; i < NTOK; i += 256) m = max(m, nearp[i]);
    sm[tid] = m;
    __syncthreads();
    for (int s = 128; s > 0; s >>= 1) {
        if (tid < s) sm[tid] = max(sm[tid], sm[tid+s]);
        __syncthreads();
    }
    if (tid == 0) *out = sm[0];
}

__global__ void qkin_kernel(const float* __restrict__ x, const int* __restrict__ nearp,
                            const int* __restrict__ maxn, const float* __restrict__ emb,
                            float* __restrict__ out)
{
    int t = blockIdx.x, c = threadIdx.x;
    float nf = (float)nearp[t], mf = (float)(*maxn);
    int ni = (int)((nf / mf) * 9.0f);
    if (ni > 9) ni = 9;
    out[t * CDIM + c] = x[t * CDIM + c] + emb[ni * CDIM + c];
}

// flash attention + additive bias |gp_i-gp_j|; 64 queries/block, 4 warps split keys
__global__ __launch_bounds__(128) void attn_kernel(
    const float* __restrict__ Q, const float* __restrict__ Km,
    const float* __restrict__ V, const float* __restrict__ gp,
    float* __restrict__ O)
{
    __shared__ float sbuf[8704];
    float* Ks = sbuf;
    float* Vs = sbuf + 64 * 36;
    float* gks = sbuf + 2 * 64 * 36;

    int h = blockIdx.y, qb = blockIdx.x, tid = threadIdx.x;
    int w = tid >> 5, lane = tid & 31;
    int r0 = qb * 64 + lane, r1 = r0 + 32;
    const float scale = 0.17677669529663687f;

    float q0[32], q1[32], o0[32], o1[32];
    #pragma unroll
    for (int d = 0; d < 32; d++) {
        q0[d] = Q[r0 * CDIM + h * 32 + d] * scale;
        q1[d] = Q[r1 * CDIM + h * 32 + d] * scale;
        o0[d] = 0.f; o1[d] = 0.f;
    }
    float gq0 = gp[h * NTOK + r0], gq1 = gp[h * NTOK + r1];
    float m0 = -1e30f, m1 = -1e30f, l0 = 0.f, l1 = 0.f;

    for (int kt = 0; kt < 49; kt++) {
        __syncthreads();
        {
            int rrow = tid & 63;
            int gr = kt * 64 + rrow;
            const float* srcp = (tid < 64 ? Km : V) + (size_t)gr * CDIM + h * 32;
            float* dstp = (tid < 64 ? Ks : Vs) + rrow * 36;
            #pragma unroll
            for (int d4 = 0; d4 < 32; d4 += 4) {
                float4 t = *(const float4*)(srcp + d4);
                *(float4*)(dstp + d4) = t;
            }
            if (tid < 64) gks[rrow] = gp[h * NTOK + gr];
        }
        __syncthreads();
        int jbase = w << 4;
        for (int jc = 0; jc < 16; jc += 4) {
            const float* kp = Ks + (jbase + jc) * 36;
            const float* vp = Vs + (jbase + jc) * 36;
            float s0[4] = {0,0,0,0}, s1[4] = {0,0,0,0};
            #pragma unroll
            for (int d4 = 0; d4 < 32; d4 += 4) {
                float4 k0 = *(const float4*)(kp + d4);
                float4 k1 = *(const float4*)(kp + 36 + d4);
                float4 k2 = *(const float4*)(kp + 72 + d4);
                float4 k3 = *(const float4*)(kp + 108 + d4);
                s0[0]=fmaf(q0[d4+0],k0.x,s0[0]); s0[0]=fmaf(q0[d4+1],k0.y,s0[0]);
                s0[0]=fmaf(q0[d4+2],k0.z,s0[0]); s0[0]=fmaf(q0[d4+3],k0.w,s0[0]);
                s0[1]=fmaf(q0[d4+0],k1.x,s0[1]); s0[1]=fmaf(q0[d4+1],k1.y,s0[1]);
                s0[1]=fmaf(q0[d4+2],k1.z,s0[1]); s0[1]=fmaf(q0[d4+3],k1.w,s0[1]);
                s0[2]=fmaf(q0[d4+0],k2.x,s0[2]); s0[2]=fmaf(q0[d4+1],k2.y,s0[2]);
                s0[2]=fmaf(q0[d4+2],k2.z,s0[2]); s0[2]=fmaf(q0[d4+3],k2.w,s0[2]);
                s0[3]=fmaf(q0[d4+0],k3.x,s0[3]); s0[3]=fmaf(q0[d4+1],k3.y,s0[3]);
                s0[3]=fmaf(q0[d4+2],k3.z,s0[3]); s0[3]=fmaf(q0[d4+3],k3.w,s0[3]);
                s1[0]=fmaf(q1[d4+0],k0.x,s1[0]); s1[0]=fmaf(q1[d4+1],k0.y,s1[0]);
                s1[0]=fmaf(q1[d4+2],k0.z,s1[0]); s1[0]=fmaf(q1[d4+3],k0.w,s1[0]);
                s1[1]=fmaf(q1[d4+0],k1.x,s1[1]); s1[1]=fmaf(q1[d4+1],k1.y,s1[1]);
                s1[1]=fmaf(q1[d4+2],k1.z,s1[1]); s1[1]=fmaf(q1[d4+3],k1.w,s1[1]);
                s1[2]=fmaf(q1[d4+0],k2.x,s1[2]); s1[2]=fmaf(q1[d4+1],k2.y,s1[2]);
                s1[2]=fmaf(q1[d4+2],k2.z,s1[2]); s1[2]=fmaf(q1[d4+3],k2.w,s1[2]);
                s1[3]=fmaf(q1[d4+0],k3.x,s1[3]); s1[3]=fmaf(q1[d4+1],k3.y,s1[3]);
                s1[3]=fmaf(q1[d4+2],k3.z,s1[3]); s1[3]=fmaf(q1[d4+3],k3.w,s1[3]);
            }
            #pragma unroll
            for (int u = 0; u < 4; u++) {
                float g = gks[jbase + jc + u];
                s0[u] += fabsf(gq0 - g);
                s1[u] += fabsf(gq1 - g);
            }
            float p0[4], p1[4];
            {
                float mn = m0;
                #pragma unroll
                for (int u = 0; u < 4; u++) mn = fmaxf(mn, s0[u]);
                if (mn > m0) {
                    float corr = fexp(m0 - mn);
                    l0 *= corr;
                    #pragma unroll
                    for (int d = 0; d < 32; d++) o0[d] *= corr;
                    m0 = mn;
                }
                #pragma unroll
                for (int u = 0; u < 4; u++) { p0[u] = fexp(s0[u] - m0); l0 += p0[u]; }
            }
            {
                float mn = m1;
                #pragma unroll
                for (int u = 0; u < 4; u++) mn = fmaxf(mn, s1[u]);
                if (mn > m1) {
                    float corr = fexp(m1 - mn);
                    l1 *= corr;
                    #pragma unroll
                    for (int d = 0; d < 32; d++) o1[d] *= corr;
                    m1 = mn;
                }
                #pragma unroll
                for (int u = 0; u < 4; u++) { p1[u] = fexp(s1[u] - m1); l1 += p1[u]; }
            }
            #pragma unroll
            for (int d4 = 0; d4 < 32; d4 += 4) {
                float4 v0 = *(const float4*)(vp + d4);
                float4 v1 = *(const float4*)(vp + 36 + d4);
                float4 v2 = *(const float4*)(vp + 72 + d4);
                float4 v3 = *(const float4*)(vp + 108 + d4);
                float t;
                t = o0[d4+0]; t=fmaf(p0[0],v0.x,t); t=fmaf(p0[1],v1.x,t); t=fmaf(p0[2],v2.x,t); t=fmaf(p0[3],v3.x,t); o0[d4+0]=t;
                t = o0[d4+1]; t=fmaf(p0[0],v0.y,t); t=fmaf(p0[1],v1.y,t); t=fmaf(p0[2],v2.y,t); t=fmaf(p0[3],v3.y,t); o0[d4+1]=t;
                t = o0[d4+2]; t=fmaf(p0[0],v0.z,t); t=fmaf(p0[1],v1.z,t); t=fmaf(p0[2],v2.z,t); t=fmaf(p0[3],v3.z,t); o0[d4+2]=t;
                t = o0[d4+3]; t=fmaf(p0[0],v0.w,t); t=fmaf(p0[1],v1.w,t); t=fmaf(p0[2],v2.w,t); t=fmaf(p0[3],v3.w,t); o0[d4+3]=t;
                t = o1[d4+0]; t=fmaf(p1[0],v0.x,t); t=fmaf(p1[1],v1.x,t); t=fmaf(p1[2],v2.x,t); t=fmaf(p1[3],v3.x,t); o1[d4+0]=t;
                t = o1[d4+1]; t=fmaf(p1[0],v0.y,t); t=fmaf(p1[1],v1.y,t); t=fmaf(p1[2],v2.y,t); t=fmaf(p1[3],v3.y,t); o1[d4+1]=t;
                t = o1[d4+2]; t=fmaf(p1[0],v0.z,t); t=fmaf(p1[1],v1.z,t); t=fmaf(p1[2],v2.z,t); t=fmaf(p1[3],v3.z,t); o1[d4+2]=t;
                t = o1[d4+3]; t=fmaf(p1[0],v0.w,t); t=fmaf(p1[1],v1.w,t); t=fmaf(p1[2],v2.w,t); t=fmaf(p1[3],v3.w,t); o1[d4+3]=t;
            }
        }
    }
    __syncthreads();
    {
        float* red = sbuf;
        int b0 = (w * 64 + lane) * 34;
        #pragma unroll
        for (int d = 0; d < 32; d++) red[b0 + d] = o0[d];
        red[b0 + 32] = m0; red[b0 + 33] = l0;
        int b1 = (w * 64 + lane + 32) * 34;
        #pragma unroll
        for (int d = 0; d < 32; d++) red[b1 + d] = o1[d];
        red[b1 + 32] = m1; red[b1 + 33] = l1;
    }
    __syncthreads();
    if (tid < 64) {
        const float* red = sbuf;
        float mw[4], M = -1e30f;
        #pragma unroll
        for (int u = 0; u < 4; u++) { mw[u] = red[(u*64+tid)*34 + 32]; M = fmaxf(M, mw[u]); }
        float cw[4], L = 0.f;
        #pragma unroll
        for (int u = 0; u < 4; u++) { cw[u] = fexp(mw[u] - M); L += cw[u] * red[(u*64+tid)*34 + 33]; }
        float inv = 1.f / L;
        int row = qb * 64 + tid;
        #pragma unroll
        for (int d = 0; d < 32; d++) {
            float s = 0.f;
            #pragma unroll
            for (int u = 0; u < 4; u++) s = fmaf(cw[u], red[(u*64+tid)*34 + d], s);
            O[row * CDIM + h * 32 + d] = s * inv;
        }
    }
}

// out = LN(a [+ b]); FINAL=1: transposed store [C][N]
template<int FINAL>
__global__ __launch_bounds__(256) void add_ln_kernel(
    const float* __restrict__ a, const float* __restrict__ b,
    const float* __restrict__ g, const float* __restrict__ be,
    float* __restrict__ out)
{
    __shared__ float red[8];
    int row = blockIdx.x, tid = threadIdx.x;
    float v = a[row * CDIM + tid];
    if (!FINAL) v += b[row * CDIM + tid];
    float s = v;
    #pragma unroll
    for (int o = 16; o; o >>= 1) s += __shfl_xor_sync(0xffffffffu, s, o);
    if ((tid & 31) == 0) red[tid >> 5] = s;
    __syncthreads();
    float mean = 0.f;
    #pragma unroll
    for (int i = 0; i < 8; i++) mean += red[i];
    mean *= (1.f / 256.f);
    float d = v - mean;
    __syncthreads();
    s = d * d;
    #pragma unroll
    for (int o = 16; o; o >>= 1) s += __shfl_xor_sync(0xffffffffu, s, o);
    if ((tid & 31) == 0) red[tid >> 5] = s;
    __syncthreads();
    float var = 0.f;
    #pragma unroll
    for (int i = 0; i < 8; i++) var += red[i];
    var *= (1.f / 256.f);
    float r = d * rsqrtf(var + 1e-5f) * g[tid] + be[tid];
    if (FINAL) out[tid * NTOK + row] = r;
    else       out[row * CDIM + tid] = r;
}

extern "C" void kernel_launch(void* const* d_in, const int* in_sizes, int n_in,
                              void* d_out, int out_size)
{
    (void)in_sizes; (void)n_in; (void)out_size;
    const float* src  = (const float*)d_in[0];
    const float* c1w  = (const float*)d_in[1];
    const float* c1b  = (const float*)d_in[2];
    const float* c2w  = (const float*)d_in[3];
    const float* c2b  = (const float*)d_in[4];
    const float* nemb = (const float*)d_in[5];
    const float* Wq   = (const float*)d_in[6];
    const float* bq   = (const float*)d_in[7];
    const float* Wk   = (const float*)d_in[8];
    const float* bk   = (const float*)d_in[9];
    const float* Wv   = (const float*)d_in[10];
    const float* bv   = (const float*)d_in[11];
    const float* Wo   = (const float*)d_in[12];
    const float* bo   = (const float*)d_in[13];
    const float* W1   = (const float*)d_in[14];
    const float* b1   = (const float*)d_in[15];
    const float* W2   = (const float*)d_in[16];
    const float* b2   = (const float*)d_in[17];
    const float* ln1g = (const float*)d_in[18];
    const float* ln1b = (const float*)d_in[19];
    const float* ln2g = (const float*)d_in[20];
    const float* ln2b = (const float*)d_in[21];
    const float* ng   = (const float*)d_in[22];
    const float* nb   = (const float*)d_in[23];

    float *c1, *gp, *x, *sqv, *d2, *qkin, *q, *k, *v, *att, *ffh, *yb;
    int *nearp, *maxn;
    cudaGetSymbolAddress((void**)&c1,    g_c1);
    cudaGetSymbolAddress((void**)&gp,    g_gp);
    cudaGetSymbolAddress((void**)&x,     g_x);
    cudaGetSymbolAddress((void**)&sqv,   g_sq);
    cudaGetSymbolAddress((void**)&d2,    g_d2);
    cudaGetSymbolAddress((void**)&nearp, g_near);
    cudaGetSymbolAddress((void**)&maxn,  g_maxnear);
    cudaGetSymbolAddress((void**)&qkin,  g_qkin);
    cudaGetSymbolAddress((void**)&q,     g_q);
    cudaGetSymbolAddress((void**)&k,     g_k);
    cudaGetSymbolAddress((void**)&v,     g_v);
    cudaGetSymbolAddress((void**)&att,   g_att);
    cudaGetSymbolAddress((void**)&ffh,   g_ffh);
    cudaGetSymbolAddress((void**)&yb,    g_y);

    pad_kernel<<<64, 256>>>(x, sqv);
    transpose_kernel<<<dim3(98, 8), dim3(32, 32)>>>(src, x);
    conv1_kernel<<<dim3(32, 49), 64>>>(src, c1w, c1b, c1);
    conv2_kernel<<<dim3(8, 49), 64>>>(c1, c2w, c2b, gp);

    for (int i = 0; i < NLAYER; i++) {
        sq_kernel<<<392, 256>>>(x, sqv);
        d2_tf32_kernel<<<dim3(25, 25), 256>>>(x, sqv, d2);
        zero_kernel<<<13, 256>>>(nearp, maxn);
        topk_kernel<<<NTOK, 256>>>(d2, nearp);
        maxnear_kernel<<<1, 256>>>(nearp, maxn);
        qkin_kernel<<<NTOK, 256>>>(x, nearp, maxn, nemb, qkin);

        mma3_gemm<0><<<dim3(50, 4), 128>>>(qkin, Wq + i*CDIM*CDIM, bq + i*CDIM, q, CDIM, CDIM);
        mma3_gemm<0><<<dim3(50, 4), 128>>>(qkin, Wk + i*CDIM*CDIM, bk + i*CDIM, k, CDIM, CDIM);
        mma3_gemm<0><<<dim3(50, 4), 128>>>(x,    Wv + i*CDIM*CDIM, bv + i*CDIM, v, CDIM, CDIM);

        attn_kernel<<<dim3(49, NHEAD), 128>>>(q, k, v, gp, att);

        mma3_gemm<0><<<dim3(50, 4), 128>>>(att, Wo + i*CDIM*CDIM, bo + i*CDIM, yb, CDIM, CDIM);
        add_ln_kernel<0><<<NTOK, 256>>>(x, yb, ln1g + i*CDIM, ln1b + i*CDIM, x);

        mma3_gemm<1><<<dim3(50, 16), 128>>>(x, W1 + i*DFFN*CDIM, b1 + i*DFFN, ffh, DFFN, CDIM);
        mma3_gemm<0><<<dim3(50, 4), 128>>>(ffh, W2 + i*CDIM*DFFN, b2 + i*CDIM, yb, CDIM, DFFN);
        add_ln_kernel<0><<<NTOK, 256>>>(x, yb, ln2g + i*CDIM, ln2b + i*CDIM, x);
    }

    add_ln_kernel<1><<<NTOK, 256>>>(x, nullptr, ng, nb, (float*)d_out);
}

// round 10
// speedup vs baseline: 1.4971x; 1.4971x over previous
#include <cuda_runtime.h>
#include <cuda_bf16.h>
#include <cstdint>
#include <math.h>

#define NTOK 3136
#define NPAD 3200
#define CDIM 256
#define NHEAD 8
#define DFFN 1024
#define NLAYER 4
#define TOPKK 16
#define HW 56

__device__ float g_c1[128 * NTOK];
__device__ float g_gp[NHEAD * NTOK];
__device__ float g_x[NPAD * CDIM];
__device__ float g_sq[NPAD];
__device__ float g_d2[(size_t)NPAD * NPAD];
__device__ int   g_near[NTOK];
__device__ int   g_maxnear[1];
__device__ float g_qkin[NPAD * CDIM];
__device__ float g_q[NPAD * CDIM];
__device__ float g_k[NPAD * CDIM];
__device__ float g_v[NPAD * CDIM];
__device__ float g_att[NPAD * CDIM];
__device__ float g_ffh[(size_t)NPAD * DFFN];
__device__ float g_y[NPAD * CDIM];

__device__ __forceinline__ float fexp(float x) {
    x = fmaxf(x, -87.0f);
    float y = x * 1.44269504088896341f;
    float r = rintf(y);
    float f = y - r;
    float p = 1.33335581e-3f;
    p = fmaf(p, f, 9.61812911e-3f);
    p = fmaf(p, f, 5.55041087e-2f);
    p = fmaf(p, f, 2.40226507e-1f);
    p = fmaf(p, f, 6.93147181e-1f);
    p = fmaf(p, f, 1.0f);
    return __int_as_float(__float_as_int(p) + (((int)r) << 23));
}

__device__ __forceinline__ unsigned f2tf32(float v) {
    unsigned r;
    asm("cvt.rna.tf32.f32 %0, %1;" : "=r"(r) : "f"(v));
    return r;
}

__device__ __forceinline__ void mma_tf32(float c[4],
    unsigned a0, unsigned a1, unsigned a2, unsigned a3,
    unsigned b0, unsigned b1)
{
    asm volatile(
        "mma.sync.aligned.m16n8k8.row.col.f32.tf32.tf32.f32 "
        "{%0,%1,%2,%3}, {%4,%5,%6,%7}, {%8,%9}, {%0,%1,%2,%3};\n"
        : "+f"(c[0]), "+f"(c[1]), "+f"(c[2]), "+f"(c[3])
        : "r"(a0), "r"(a1), "r"(a2), "r"(a3), "r"(b0), "r"(b1));
}

__global__ void pad_kernel(float* __restrict__ x, float* __restrict__ sqv) {
    int i = blockIdx.x * 256 + threadIdx.x;
    x[NTOK * CDIM + i] = 0.f;
    if (i < NPAD - NTOK) sqv[NTOK + i] = 0.f;
}

__global__ void transpose_kernel(const float* __restrict__ src, float* __restrict__ dst) {
    __shared__ float tile[32][33];
    int t0 = blockIdx.x * 32, c0 = blockIdx.y * 32;
    int tx = threadIdx.x, ty = threadIdx.y;
    tile[ty][tx] = src[(c0 + ty) * NTOK + t0 + tx];
    __syncthreads();
    dst[(t0 + ty) * CDIM + c0 + tx] = tile[tx][ty];
}

__global__ __launch_bounds__(64) void conv1_kernel(
    const float* __restrict__ src, const float* __restrict__ wt,
    const float* __restrict__ bias, float* __restrict__ out)
{
    __shared__ float ws[4 * 2304];
    int cog = blockIdx.x;
    int p = blockIdx.y * 64 + threadIdx.x;
    for (int i = threadIdx.x; i < 4 * 2304; i += 64) ws[i] = wt[cog * 4 * 2304 + i];
    __syncthreads();
    int y = p / HW, x = p % HW;
    float a[4][2];
    #pragma unroll
    for (int j = 0; j < 4; j++) { a[j][0] = 0.f; a[j][1] = 0.f; }
    for (int ci = 0; ci < 256; ci += 2) {
        #pragma unroll
        for (int par = 0; par < 2; par++) {
            const float* ip = src + (ci + par) * NTOK;
            const float* wp = ws + (ci + par) * 9;
            #pragma unroll
            for (int dy = 0; dy < 3; dy++) {
                int yy = y + dy - 1; if ((unsigned)yy >= HW) continue;
                #pragma unroll
                for (int dx = 0; dx < 3; dx++) {
                    int xx = x + dx - 1; if ((unsigned)xx >= HW) continue;
                    float v = ip[yy * HW + xx]; int wi = dy * 3 + dx;
                    a[0][par] = fmaf(v, wp[wi],          a[0][par]);
                    a[1][par] = fmaf(v, wp[2304 + wi],   a[1][par]);
                    a[2][par] = fmaf(v, wp[4608 + wi],   a[2][par]);
                    a[3][par] = fmaf(v, wp[6912 + wi],   a[3][par]);
                }
            }
        }
    }
    #pragma unroll
    for (int j = 0; j < 4; j++)
        out[(cog*4+j)*NTOK + p] = fmaxf(a[j][0] + a[j][1] + bias[cog*4+j], 0.f);
}

__global__ __launch_bounds__(64) void conv2_kernel(
    const float* __restrict__ c1, const float* __restrict__ wt,
    const float* __restrict__ bias, float* __restrict__ gp)
{
    __shared__ float ws[1152];
    int co = blockIdx.x;
    int p = blockIdx.y * 64 + threadIdx.x;
    for (int i = threadIdx.x; i < 1152; i += 64) ws[i] = wt[co * 1152 + i];
    __syncthreads();
    int y = p / HW, x = p % HW;
    float a0 = 0.f, a1 = 0.f, a2 = 0.f, a3 = 0.f;
    for (int ci = 0; ci < 128; ci += 4) {
        #pragma unroll
        for (int dy = 0; dy < 3; dy++) {
            int yy = y + dy - 1; if ((unsigned)yy >= HW) continue;
            #pragma unroll
            for (int dx = 0; dx < 3; dx++) {
                int xx = x + dx - 1; if ((unsigned)xx >= HW) continue;
                int po = yy * HW + xx, wi = dy * 3 + dx;
                a0 = fmaf(c1[(ci+0) * NTOK + po], ws[(ci+0) * 9 + wi], a0);
                a1 = fmaf(c1[(ci+1) * NTOK + po], ws[(ci+1) * 9 + wi], a1);
                a2 = fmaf(c1[(ci+2) * NTOK + po], ws[(ci+2) * 9 + wi], a2);
                a3 = fmaf(c1[(ci+3) * NTOK + po], ws[(ci+3) * 9 + wi], a3);
            }
        }
    }
    float a = bias[co] + ((a0 + a1) + (a2 + a3));
    gp[co * NTOK + p] = 1.0f / (1.0f + __expf(-a));
}

__global__ __launch_bounds__(256) void sq_kernel(const float* __restrict__ x,
                                                 float* __restrict__ sq)
{
    int row = blockIdx.x * 8 + (threadIdx.x >> 5);
    int lane = threadIdx.x & 31;
    const float* r = x + row * CDIM;
    float s = 0.f;
    #pragma unroll
    for (int i = 0; i < 8; i++) { float v = r[lane + i * 32]; s = fmaf(v, v, s); }
    #pragma unroll
    for (int o = 16; o; o >>= 1) s += __shfl_xor_sync(0xffffffffu, s, o);
    if (lane == 0) sq[row] = s;
}

__global__ __launch_bounds__(256) void d2_tf32_kernel(
    const float* __restrict__ X, const float* __restrict__ sqv,
    float* __restrict__ C)
{
    __shared__ float As[128 * 36];
    __shared__ float Bs[128 * 36];
    const int tid = threadIdx.x;
    const int wid = tid >> 5, lane = tid & 31;
    const int warpM = wid >> 2, warpN = wid & 3;
    const int i0 = blockIdx.x * 128, j0 = blockIdx.y * 128;
    const int gid = lane >> 2, qid = lane & 3;

    float acc[4][4][4];
    #pragma unroll
    for (int a = 0; a < 4; a++)
        #pragma unroll
        for (int b = 0; b < 4; b++)
            #pragma unroll
            for (int c = 0; c < 4; c++) acc[a][b][c] = 0.f;

    const int lrow = tid >> 1;
    const int lk = (tid & 1) * 16;
    const float* Ag = X + (size_t)(i0 + lrow) * CDIM + lk;
    const float* Bg = X + (size_t)(j0 + lrow) * CDIM + lk;
    float* Asw = As + lrow * 36 + lk;
    float* Bsw = Bs + lrow * 36 + lk;

    for (int k0 = 0; k0 < CDIM; k0 += 32) {
        __syncthreads();
        #pragma unroll
        for (int q = 0; q < 4; q++) {
            float4 av = *(const float4*)(Ag + k0 + q * 4);
            float4 bv = *(const float4*)(Bg + k0 + q * 4);
            float4 at, bt;
            at.x = __uint_as_float(f2tf32(av.x)); at.y = __uint_as_float(f2tf32(av.y));
            at.z = __uint_as_float(f2tf32(av.z)); at.w = __uint_as_float(f2tf32(av.w));
            bt.x = __uint_as_float(f2tf32(bv.x)); bt.y = __uint_as_float(f2tf32(bv.y));
            bt.z = __uint_as_float(f2tf32(bv.z)); bt.w = __uint_as_float(f2tf32(bv.w));
            *(float4*)&Asw[q * 4] = at;
            *(float4*)&Bsw[q * 4] = bt;
        }
        __syncthreads();
        #pragma unroll
        for (int k8 = 0; k8 < 4; k8++) {
            unsigned af[4][4], bf[4][2];
            #pragma unroll
            for (int tm = 0; tm < 4; tm++) {
                const float* p = As + (warpM * 64 + tm * 16 + gid) * 36 + k8 * 8 + qid;
                af[tm][0] = __float_as_uint(p[0]);
                af[tm][1] = __float_as_uint(p[8 * 36]);
                af[tm][2] = __float_as_uint(p[4]);
                af[tm][3] = __float_as_uint(p[8 * 36 + 4]);
            }
            #pragma unroll
            for (int tn = 0; tn < 4; tn++) {
                const float* p = Bs + (warpN * 32 + tn * 8 + gid) * 36 + k8 * 8 + qid;
                bf[tn][0] = __float_as_uint(p[0]);
                bf[tn][1] = __float_as_uint(p[4]);
            }
            #pragma unroll
            for (int tm = 0; tm < 4; tm++)
                #pragma unroll
                for (int tn = 0; tn < 4; tn++)
                    mma_tf32(acc[tm][tn], af[tm][0], af[tm][1], af[tm][2], af[tm][3],
                             bf[tn][0], bf[tn][1]);
        }
    }

    #pragma unroll
    for (int tm = 0; tm < 4; tm++) {
        const int r0 = i0 + warpM * 64 + tm * 16 + gid;
        const float sr0 = sqv[r0], sr1 = sqv[r0 + 8];
        #pragma unroll
        for (int tn = 0; tn < 4; tn++) {
            const int c0i = j0 + warpN * 32 + tn * 8 + qid * 2;
            const float sc0 = sqv[c0i], sc1 = sqv[c0i + 1];
            float2 v0, v1;
            v0.x = sr0 + sc0 - 2.f * acc[tm][tn][0];
            v0.y = sr0 + sc1 - 2.f * acc[tm][tn][1];
            v1.x = sr1 + sc0 - 2.f * acc[tm][tn][2];
            v1.y = sr1 + sc1 - 2.f * acc[tm][tn][3];
            *(float2*)&C[(size_t)r0 * NPAD + c0i] = v0;
            *(float2*)&C[(size_t)(r0 + 8) * NPAD + c0i] = v1;
        }
    }
}

template<int EPI>
__global__ __launch_bounds__(128) void mma3_gemm(
    const float* __restrict__ A, const float* __restrict__ B,
    const float* __restrict__ bias, float* __restrict__ C,
    int Nn, int K)
{
    __shared__ float Ah[64 * 36], Al[64 * 36], Bh[64 * 36], Bl[64 * 36];
    const int tid = threadIdx.x;
    const int wid = tid >> 5, lane = tid & 31;
    const int warpM = wid >> 1, warpN = wid & 1;
    const int i0 = blockIdx.x * 64, j0 = blockIdx.y * 64;
    const int gid = lane >> 2, qid = lane & 3;

    float acc[2][4][4];
    #pragma unroll
    for (int a = 0; a < 2; a++)
        #pragma unroll
        for (int b = 0; b < 4; b++)
            #pragma unroll
            for (int c = 0; c < 4; c++) acc[a][b][c] = 0.f;

    const int lrow = tid >> 1;
    const int lk = (tid & 1) * 16;
    const float* Ag = A + (size_t)(i0 + lrow) * K + lk;
    const float* Bg = B + (size_t)(j0 + lrow) * K + lk;
    const int sbase = lrow * 36 + lk;

    for (int k0 = 0; k0 < K; k0 += 32) {
        __syncthreads();
        #pragma unroll
        for (int q = 0; q < 4; q++) {
            float4 av = *(const float4*)(Ag + k0 + q * 4);
            float4 bv = *(const float4*)(Bg + k0 + q * 4);
            float4 avh, avl, bvh, bvl;
            avh.x = __uint_as_float(f2tf32(av.x)); avl.x = __uint_as_float(f2tf32(av.x - avh.x));
            avh.y = __uint_as_float(f2tf32(av.y)); avl.y = __uint_as_float(f2tf32(av.y - avh.y));
            avh.z = __uint_as_float(f2tf32(av.z)); avl.z = __uint_as_float(f2tf32(av.z - avh.z));
            avh.w = __uint_as_float(f2tf32(av.w)); avl.w = __uint_as_float(f2tf32(av.w - avh.w));
            bvh.x = __uint_as_float(f2tf32(bv.x)); bvl.x = __uint_as_float(f2tf32(bv.x - bvh.x));
            bvh.y = __uint_as_float(f2tf32(bv.y)); bvl.y = __uint_as_float(f2tf32(bv.y - bvh.y));
            bvh.z = __uint_as_float(f2tf32(bv.z)); bvl.z = __uint_as_float(f2tf32(bv.z - bvh.z));
            bvh.w = __uint_as_float(f2tf32(bv.w)); bvl.w = __uint_as_float(f2tf32(bv.w - bvh.w));
            *(float4*)&Ah[sbase + q * 4] = avh;
            *(float4*)&Al[sbase + q * 4] = avl;
            *(float4*)&Bh[sbase + q * 4] = bvh;
            *(float4*)&Bl[sbase + q * 4] = bvl;
        }
        __syncthreads();
        #pragma unroll
        for (int k8 = 0; k8 < 4; k8++) {
            unsigned afh[2][4], afl[2][4], bfh[4][2], bfl[4][2];
            #pragma unroll
            for (int tm = 0; tm < 2; tm++) {
                const int off = (warpM * 32 + tm * 16 + gid) * 36 + k8 * 8 + qid;
                afh[tm][0] = __float_as_uint(Ah[off]);
                afh[tm][1] = __float_as_uint(Ah[off + 8 * 36]);
                afh[tm][2] = __float_as_uint(Ah[off + 4]);
                afh[tm][3] = __float_as_uint(Ah[off + 8 * 36 + 4]);
                afl[tm][0] = __float_as_uint(Al[off]);
                afl[tm][1] = __float_as_uint(Al[off + 8 * 36]);
                afl[tm][2] = __float_as_uint(Al[off + 4]);
                afl[tm][3] = __float_as_uint(Al[off + 8 * 36 + 4]);
            }
            #pragma unroll
            for (int tn = 0; tn < 4; tn++) {
                const int off = (warpN * 32 + tn * 8 + gid) * 36 + k8 * 8 + qid;
                bfh[tn][0] = __float_as_uint(Bh[off]);
                bfh[tn][1] = __float_as_uint(Bh[off + 4]);
                bfl[tn][0] = __float_as_uint(Bl[off]);
                bfl[tn][1] = __float_as_uint(Bl[off + 4]);
            }
            #pragma unroll
            for (int tm = 0; tm < 2; tm++)
                #pragma unroll
                for (int tn = 0; tn < 4; tn++) {
                    mma_tf32(acc[tm][tn], afh[tm][0], afh[tm][1], afh[tm][2], afh[tm][3],
                             bfh[tn][0], bfh[tn][1]);
                    mma_tf32(acc[tm][tn], afh[tm][0], afh[tm][1], afh[tm][2], afh[tm][3],
                             bfl[tn][0], bfl[tn][1]);
                    mma_tf32(acc[tm][tn], afl[tm][0], afl[tm][1], afl[tm][2], afl[tm][3],
                             bfh[tn][0], bfh[tn][1]);
                }
        }
    }

    #pragma unroll
    for (int tm = 0; tm < 2; tm++) {
        const int r0 = i0 + warpM * 32 + tm * 16 + gid;
        #pragma unroll
        for (int tn = 0; tn < 4; tn++) {
            const int c0i = j0 + warpN * 32 + tn * 8 + qid * 2;
            const float b0 = bias[c0i], b1 = bias[c0i + 1];
            float2 v0, v1;
            v0.x = acc[tm][tn][0] + b0; v0.y = acc[tm][tn][1] + b1;
            v1.x = acc[tm][tn][2] + b0; v1.y = acc[tm][tn][3] + b1;
            if (EPI == 1) {
                v0.x = fmaxf(v0.x, 0.f); v0.y = fmaxf(v0.y, 0.f);
                v1.x = fmaxf(v1.x, 0.f); v1.y = fmaxf(v1.y, 0.f);
            }
            *(float2*)&C[(size_t)r0 * Nn + c0i] = v0;
            *(float2*)&C[(size_t)(r0 + 8) * Nn + c0i] = v1;
        }
    }
}

__global__ void zero_kernel(int* __restrict__ nearp, int* __restrict__ maxn) {
    int i = blockIdx.x * 256 + threadIdx.x;
    if (i < NTOK) nearp[i] = 0;
    if (i == 0) *maxn = 0;
}

__global__ __launch_bounds__(256) void topk_kernel(const float* __restrict__ d2,
                                                   int* __restrict__ nearp)
{
    __shared__ float vals[NTOK];
    __shared__ float rv[256];
    __shared__ int   ri[256];
    int row = blockIdx.x, tid = threadIdx.x;
    const float* rp = d2 + (size_t)row * NPAD;
    for (int i = tid; i < NTOK; i += 256) vals[i] = rp[i];
    __syncthreads();
    for (int it = 0; it < TOPKK; it++) {
        float bv = 3.0e38f; int bi = 0x7FFFFFFF;
        for (int i = tid; i < NTOK; i += 256) {
            float v = vals[i];
            if (v < bv) { bv = v; bi = i; }
        }
        rv[tid] = bv; ri[tid] = bi;
        __syncthreads();
        for (int s = 128; s > 0; s >>= 1) {
            if (tid < s) {
                float ov = rv[tid+s]; int oi = ri[tid+s];
                if (ov < rv[tid] || (ov == rv[tid] && oi < ri[tid])) { rv[tid]=ov; ri[tid]=oi; }
            }
            __syncthreads();
        }
        if (tid == 0) { atomicAdd(&nearp[ri[0]], 1); vals[ri[0]] = 3.0e38f; }
        __syncthreads();
    }
}

__global__ __launch_bounds__(256) void maxnear_kernel(const int* __restrict__ nearp,
                                                      int* __restrict__ out)
{
    __shared__ int sm[256];
    int tid = threadIdx.x;
    int m = 0;
    for (int i = tid; i < NTOK; i += 256) m = max(m, nearp[i]);
    sm[tid] = m;
    __syncthreads();
    for (int s = 128; s > 0; s >>= 1) {
        if (tid < s) sm[tid] = max(sm[tid], sm[tid+s]);
        __syncthreads();
    }
    if (tid == 0) *out = sm[0];
}

__global__ void qkin_kernel(const float* __restrict__ x, const int* __restrict__ nearp,
                            const int* __restrict__ maxn, const float* __restrict__ emb,
                            float* __restrict__ out)
{
    int t = blockIdx.x, c = threadIdx.x;
    float nf = (float)nearp[t], mf = (float)(*maxn);
    int ni = (int)((nf / mf) * 9.0f);
    if (ni > 9) ni = 9;
    out[t * CDIM + c] = x[t * CDIM + c] + emb[ni * CDIM + c];
}

// -----------------------------------------------------------------------------
// Flash attention on tf32 mma.sync. Block = (q-tile of 64 rows, head).
// 4 warps x 16 q-rows. Per 64-key tile: S=QK^T (8 n8 x 4 k8 MMAs), bias+online
// softmax on C fragments (row stats shfl'd over the qid quad), P->smem->A-frag,
// O += P.V (8 k8 x 4 n8 MMAs) with rescale-on-max-update.
// -----------------------------------------------------------------------------
__global__ __launch_bounds__(128) void attn_kernel(
    const float* __restrict__ Q, const float* __restrict__ Km,
    const float* __restrict__ V, const float* __restrict__ gp,
    float* __restrict__ O)
{
    __shared__ float Qs[64 * 36];
    __shared__ float Ks[64 * 36];
    __shared__ float Vts[32 * 68];
    __shared__ float Ps[4 * 16 * 68];
    __shared__ float gks[64];

    const int h = blockIdx.y, qb = blockIdx.x, tid = threadIdx.x;
    const int w = tid >> 5, lane = tid & 31;
    const int gid = lane >> 2, qid = lane & 3;
    const float scale = 0.17677669529663687f;

    for (int idx = tid; idx < 64 * 32; idx += 128) {
        int i = idx >> 5, d = idx & 31;
        float qv = Q[(size_t)(qb * 64 + i) * CDIM + h * 32 + d] * scale;
        Qs[i * 36 + d] = __uint_as_float(f2tf32(qv));
    }
    const float gq0 = gp[h * NTOK + qb * 64 + w * 16 + gid];
    const float gq1 = gp[h * NTOK + qb * 64 + w * 16 + gid + 8];

    float oacc[4][4];
    #pragma unroll
    for (int dt = 0; dt < 4; dt++)
        #pragma unroll
        for (int c = 0; c < 4; c++) oacc[dt][c] = 0.f;
    float m0 = -1e30f, m1 = -1e30f, l0 = 0.f, l1 = 0.f;
    float* Pw = Ps + w * (16 * 68);

    for (int kt = 0; kt < 49; kt++) {
        __syncthreads();
        for (int idx = tid; idx < 64 * 32; idx += 128) {
            int j = idx >> 5, d = idx & 31;
            size_t gbase = (size_t)(kt * 64 + j) * CDIM + h * 32 + d;
            Ks[j * 36 + d] = __uint_as_float(f2tf32(Km[gbase]));
            Vts[d * 68 + j] = __uint_as_float(f2tf32(V[gbase]));
        }
        if (tid < 64) gks[tid] = gp[h * NTOK + kt * 64 + tid];
        __syncthreads();

        // S = Q K^T
        float sc[8][4];
        #pragma unroll
        for (int tn = 0; tn < 8; tn++)
            #pragma unroll
            for (int c = 0; c < 4; c++) sc[tn][c] = 0.f;
        #pragma unroll
        for (int k8 = 0; k8 < 4; k8++) {
            const int aoff = (w * 16 + gid) * 36 + k8 * 8 + qid;
            unsigned a0 = __float_as_uint(Qs[aoff]);
            unsigned a1 = __float_as_uint(Qs[aoff + 8 * 36]);
            unsigned a2 = __float_as_uint(Qs[aoff + 4]);
            unsigned a3 = __float_as_uint(Qs[aoff + 8 * 36 + 4]);
            #pragma unroll
            for (int tn = 0; tn < 8; tn++) {
                const int boff = (tn * 8 + gid) * 36 + k8 * 8 + qid;
                mma_tf32(sc[tn], a0, a1, a2, a3,
                         __float_as_uint(Ks[boff]), __float_as_uint(Ks[boff + 4]));
            }
        }
        // bias + row max
        float mn0 = -1e30f, mn1 = -1e30f;
        #pragma unroll
        for (int tn = 0; tn < 8; tn++) {
            float ga = gks[tn * 8 + qid * 2], gb = gks[tn * 8 + qid * 2 + 1];
            sc[tn][0] += fabsf(gq0 - ga); sc[tn][1] += fabsf(gq0 - gb);
            sc[tn][2] += fabsf(gq1 - ga); sc[tn][3] += fabsf(gq1 - gb);
            mn0 = fmaxf(mn0, fmaxf(sc[tn][0], sc[tn][1]));
            mn1 = fmaxf(mn1, fmaxf(sc[tn][2], sc[tn][3]));
        }
        mn0 = fmaxf(mn0, __shfl_xor_sync(0xffffffffu, mn0, 1));
        mn0 = fmaxf(mn0, __shfl_xor_sync(0xffffffffu, mn0, 2));
        mn1 = fmaxf(mn1, __shfl_xor_sync(0xffffffffu, mn1, 1));
        mn1 = fmaxf(mn1, __shfl_xor_sync(0xffffffffu, mn1, 2));
        if (mn0 > m0) {
            float corr = fexp(m0 - mn0);
            l0 *= corr;
            #pragma unroll
            for (int dt = 0; dt < 4; dt++) { oacc[dt][0] *= corr; oacc[dt][1] *= corr; }
            m0 = mn0;
        }
        if (mn1 > m1) {
            float corr = fexp(m1 - mn1);
            l1 *= corr;
            #pragma unroll
            for (int dt = 0; dt < 4; dt++) { oacc[dt][2] *= corr; oacc[dt][3] *= corr; }
            m1 = mn1;
        }
        // P = exp(S - m), partial sums, store to smem as tf32
        float ps0 = 0.f, ps1 = 0.f;
        #pragma unroll
        for (int tn = 0; tn < 8; tn++) {
            float p00 = fexp(sc[tn][0] - m0), p01 = fexp(sc[tn][1] - m0);
            float p10 = fexp(sc[tn][2] - m1), p11 = fexp(sc[tn][3] - m1);
            ps0 += p00 + p01; ps1 += p10 + p11;
            int col = tn * 8 + qid * 2;
            Pw[gid * 68 + col]       = __uint_as_float(f2tf32(p00));
            Pw[gid * 68 + col + 1]   = __uint_as_float(f2tf32(p01));
            Pw[(gid + 8) * 68 + col]     = __uint_as_float(f2tf32(p10));
            Pw[(gid + 8) * 68 + col + 1] = __uint_as_float(f2tf32(p11));
        }
        ps0 += __shfl_xor_sync(0xffffffffu, ps0, 1);
        ps0 += __shfl_xor_sync(0xffffffffu, ps0, 2);
        ps1 += __shfl_xor_sync(0xffffffffu, ps1, 1);
        ps1 += __shfl_xor_sync(0xffffffffu, ps1, 2);
        l0 += ps0; l1 += ps1;
        __syncwarp();
        // O += P . V
        #pragma unroll
        for (int k8 = 0; k8 < 8; k8++) {
            const int aoff = gid * 68 + k8 * 8 + qid;
            unsigned a0 = __float_as_uint(Pw[aoff]);
            unsigned a1 = __float_as_uint(Pw[aoff + 8 * 68]);
            unsigned a2 = __float_as_uint(Pw[aoff + 4]);
            unsigned a3 = __float_as_uint(Pw[aoff + 8 * 68 + 4]);
            #pragma unroll
            for (int dt = 0; dt < 4; dt++) {
                const int boff = (dt * 8 + gid) * 68 + k8 * 8 + qid;
                mma_tf32(oacc[dt], a0, a1, a2, a3,
                         __float_as_uint(Vts[boff]), __float_as_uint(Vts[boff + 4]));
            }
        }
        __syncwarp();
    }

    const float inv0 = 1.f / l0, inv1 = 1.f / l1;
    const int r0g = qb * 64 + w * 16 + gid, r1g = r0g + 8;
    #pragma unroll
    for (int dt = 0; dt < 4; dt++) {
        const int col = h * 32 + dt * 8 + qid * 2;
        float2 v0, v1;
        v0.x = oacc[dt][0] * inv0; v0.y = oacc[dt][1] * inv0;
        v1.x = oacc[dt][2] * inv1; v1.y = oacc[dt][3] * inv1;
        *(float2*)&O[(size_t)r0g * CDIM + col] = v0;
        *(float2*)&O[(size_t)r1g * CDIM + col] = v1;
    }
}

template<int FINAL>
__global__ __launch_bounds__(256) void add_ln_kernel(
    const float* __restrict__ a, const float* __restrict__ b,
    const float* __restrict__ g, const float* __restrict__ be,
    float* __restrict__ out)
{
    __shared__ float red[8];
    int row = blockIdx.x, tid = threadIdx.x;
    float v = a[row * CDIM + tid];
    if (!FINAL) v += b[row * CDIM + tid];
    float s = v;
    #pragma unroll
    for (int o = 16; o; o >>= 1) s += __shfl_xor_sync(0xffffffffu, s, o);
    if ((tid & 31) == 0) red[tid >> 5] = s;
    __syncthreads();
    float mean = 0.f;
    #pragma unroll
    for (int i = 0; i < 8; i++) mean += red[i];
    mean *= (1.f / 256.f);
    float d = v - mean;
    __syncthreads();
    s = d * d;
    #pragma unroll
    for (int o = 16; o; o >>= 1) s += __shfl_xor_sync(0xffffffffu, s, o);
    if ((tid & 31) == 0) red[tid >> 5] = s;
    __syncthreads();
    float var = 0.f;
    #pragma unroll
    for (int i = 0; i < 8; i++) var += red[i];
    var *= (1.f / 256.f);
    float r = d * rsqrtf(var + 1e-5f) * g[tid] + be[tid];
    if (FINAL) out[tid * NTOK + row] = r;
    else       out[row * CDIM + tid] = r;
}

extern "C" void kernel_launch(void* const* d_in, const int* in_sizes, int n_in,
                              void* d_out, int out_size)
{
    (void)in_sizes; (void)n_in; (void)out_size;
    const float* src  = (const float*)d_in[0];
    const float* c1w  = (const float*)d_in[1];
    const float* c1b  = (const float*)d_in[2];
    const float* c2w  = (const float*)d_in[3];
    const float* c2b  = (const float*)d_in[4];
    const float* nemb = (const float*)d_in[5];
    const float* Wq   = (const float*)d_in[6];
    const float* bq   = (const float*)d_in[7];
    const float* Wk   = (const float*)d_in[8];
    const float* bk   = (const float*)d_in[9];
    const float* Wv   = (const float*)d_in[10];
    const float* bv   = (const float*)d_in[11];
    const float* Wo   = (const float*)d_in[12];
    const float* bo   = (const float*)d_in[13];
    const float* W1   = (const float*)d_in[14];
    const float* b1   = (const float*)d_in[15];
    const float* W2   = (const float*)d_in[16];
    const float* b2   = (const float*)d_in[17];
    const float* ln1g = (const float*)d_in[18];
    const float* ln1b = (const float*)d_in[19];
    const float* ln2g = (const float*)d_in[20];
    const float* ln2b = (const float*)d_in[21];
    const float* ng   = (const float*)d_in[22];
    const float* nb   = (const float*)d_in[23];

    float *c1, *gp, *x, *sqv, *d2, *qkin, *q, *k, *v, *att, *ffh, *yb;
    int *nearp, *maxn;
    cudaGetSymbolAddress((void**)&c1,    g_c1);
    cudaGetSymbolAddress((void**)&gp,    g_gp);
    cudaGetSymbolAddress((void**)&x,     g_x);
    cudaGetSymbolAddress((void**)&sqv,   g_sq);
    cudaGetSymbolAddress((void**)&d2,    g_d2);
    cudaGetSymbolAddress((void**)&nearp, g_near);
    cudaGetSymbolAddress((void**)&maxn,  g_maxnear);
    cudaGetSymbolAddress((void**)&qkin,  g_qkin);
    cudaGetSymbolAddress((void**)&q,     g_q);
    cudaGetSymbolAddress((void**)&k,     g_k);
    cudaGetSymbolAddress((void**)&v,     g_v);
    cudaGetSymbolAddress((void**)&att,   g_att);
    cudaGetSymbolAddress((void**)&ffh,   g_ffh);
    cudaGetSymbolAddress((void**)&yb,    g_y);

    pad_kernel<<<64, 256>>>(x, sqv);
    transpose_kernel<<<dim3(98, 8), dim3(32, 32)>>>(src, x);
    conv1_kernel<<<dim3(32, 49), 64>>>(src, c1w, c1b, c1);
    conv2_kernel<<<dim3(8, 49), 64>>>(c1, c2w, c2b, gp);

    for (int i = 0; i < NLAYER; i++) {
        sq_kernel<<<392, 256>>>(x, sqv);
        d2_tf32_kernel<<<dim3(25, 25), 256>>>(x, sqv, d2);
        zero_kernel<<<13, 256>>>(nearp, maxn);
        topk_kernel<<<NTOK, 256>>>(d2, nearp);
        maxnear_kernel<<<1, 256>>>(nearp, maxn);
        qkin_kernel<<<NTOK, 256>>>(x, nearp, maxn, nemb, qkin);

        mma3_gemm<0><<<dim3(50, 4), 128>>>(qkin, Wq + i*CDIM*CDIM, bq + i*CDIM, q, CDIM, CDIM);
        mma3_gemm<0><<<dim3(50, 4), 128>>>(qkin, Wk + i*CDIM*CDIM, bk + i*CDIM, k, CDIM, CDIM);
        mma3_gemm<0><<<dim3(50, 4), 128>>>(x,    Wv + i*CDIM*CDIM, bv + i*CDIM, v, CDIM, CDIM);

        attn_kernel<<<dim3(49, NHEAD), 128>>>(q, k, v, gp, att);

        mma3_gemm<0><<<dim3(50, 4), 128>>>(att, Wo + i*CDIM*CDIM, bo + i*CDIM, yb, CDIM, CDIM);
        add_ln_kernel<0><<<NTOK, 256>>>(x, yb, ln1g + i*CDIM, ln1b + i*CDIM, x);

        mma3_gemm<1><<<dim3(50, 16), 128>>>(x, W1 + i*DFFN*CDIM, b1 + i*DFFN, ffh, DFFN, CDIM);
        mma3_gemm<0><<<dim3(50, 4), 128>>>(ffh, W2 + i*CDIM*DFFN, b2 + i*CDIM, yb, CDIM, DFFN);
        add_ln_kernel<0><<<NTOK, 256>>>(x, yb, ln2g + i*CDIM, ln2b + i*CDIM, x);
    }

    add_ln_kernel<1><<<NTOK, 256>>>(x, nullptr, ng, nb, (float*)d_out);
}

// round 11
// speedup vs baseline: 1.7916x; 1.1967x over previous
#include <cuda_runtime.h>
#include <cuda_bf16.h>
#include <cstdint>
#include <math.h>

#define NTOK 3136
#define NPAD 3200
#define CDIM 256
#define NHEAD 8
#define DFFN 1024
#define NLAYER 4
#define TOPKK 16
#define HW 56

__device__ float g_c1[128 * NTOK];
__device__ float g_gp[NHEAD * NTOK];
__device__ float g_x[NPAD * CDIM];
__device__ float g_sq[NPAD];
__device__ float g_d2[(size_t)NPAD * NPAD];
__device__ int   g_near[NTOK];
__device__ int   g_maxnear[1];
__device__ float g_qkin[NPAD * CDIM];
__device__ float g_q[NPAD * CDIM];
__device__ float g_k[NPAD * CDIM];
__device__ float g_v[NPAD * CDIM];
__device__ float g_att[NPAD * CDIM];
__device__ float g_ffh[(size_t)NPAD * DFFN];
__device__ float g_y[NPAD * CDIM];

__device__ __forceinline__ float fexp(float x) {
    x = fmaxf(x, -87.0f);
    float y = x * 1.44269504088896341f;
    float r = rintf(y);
    float f = y - r;
    float p = 1.33335581e-3f;
    p = fmaf(p, f, 9.61812911e-3f);
    p = fmaf(p, f, 5.55041087e-2f);
    p = fmaf(p, f, 2.40226507e-1f);
    p = fmaf(p, f, 6.93147181e-1f);
    p = fmaf(p, f, 1.0f);
    return __int_as_float(__float_as_int(p) + (((int)r) << 23));
}

__device__ __forceinline__ unsigned f2tf32(float v) {
    unsigned r;
    asm("cvt.rna.tf32.f32 %0, %1;" : "=r"(r) : "f"(v));
    return r;
}

__device__ __forceinline__ void mma_tf32(float c[4],
    unsigned a0, unsigned a1, unsigned a2, unsigned a3,
    unsigned b0, unsigned b1)
{
    asm volatile(
        "mma.sync.aligned.m16n8k8.row.col.f32.tf32.tf32.f32 "
        "{%0,%1,%2,%3}, {%4,%5,%6,%7}, {%8,%9}, {%0,%1,%2,%3};\n"
        : "+f"(c[0]), "+f"(c[1]), "+f"(c[2]), "+f"(c[3])
        : "r"(a0), "r"(a1), "r"(a2), "r"(a3), "r"(b0), "r"(b1));
}

__global__ void pad_kernel(float* __restrict__ x, float* __restrict__ sqv) {
    int i = blockIdx.x * 256 + threadIdx.x;
    x[NTOK * CDIM + i] = 0.f;
    if (i < NPAD - NTOK) sqv[NTOK + i] = 0.f;
}

__global__ void transpose_kernel(const float* __restrict__ src, float* __restrict__ dst) {
    __shared__ float tile[32][33];
    int t0 = blockIdx.x * 32, c0 = blockIdx.y * 32;
    int tx = threadIdx.x, ty = threadIdx.y;
    tile[ty][tx] = src[(c0 + ty) * NTOK + t0 + tx];
    __syncthreads();
    dst[(t0 + ty) * CDIM + c0 + tx] = tile[tx][ty];
}

// conv1: 256 threads = 64 pixels x 4 ci-groups (64 ci each), smem reduce
__global__ __launch_bounds__(256) void conv1_kernel(
    const float* __restrict__ src, const float* __restrict__ wt,
    const float* __restrict__ bias, float* __restrict__ out)
{
    __shared__ float ws[4 * 2304];
    __shared__ float red[4 * 256];
    int cog = blockIdx.x;
    int tid = threadIdx.x;
    int px = tid & 63, cig = tid >> 6;
    int p = blockIdx.y * 64 + px;
    for (int i = tid; i < 4 * 2304; i += 256) ws[i] = wt[cog * 4 * 2304 + i];
    __syncthreads();
    int y = p / HW, x = p % HW;
    float a[4][2];
    #pragma unroll
    for (int j = 0; j < 4; j++) { a[j][0] = 0.f; a[j][1] = 0.f; }
    for (int ci = cig * 64; ci < cig * 64 + 64; ci += 2) {
        #pragma unroll
        for (int par = 0; par < 2; par++) {
            const float* ip = src + (ci + par) * NTOK;
            const float* wp = ws + (ci + par) * 9;
            #pragma unroll
            for (int dy = 0; dy < 3; dy++) {
                int yy = y + dy - 1; if ((unsigned)yy >= HW) continue;
                #pragma unroll
                for (int dx = 0; dx < 3; dx++) {
                    int xx = x + dx - 1; if ((unsigned)xx >= HW) continue;
                    float v = ip[yy * HW + xx]; int wi = dy * 3 + dx;
                    a[0][par] = fmaf(v, wp[wi],          a[0][par]);
                    a[1][par] = fmaf(v, wp[2304 + wi],   a[1][par]);
                    a[2][par] = fmaf(v, wp[4608 + wi],   a[2][par]);
                    a[3][par] = fmaf(v, wp[6912 + wi],   a[3][par]);
                }
            }
        }
    }
    #pragma unroll
    for (int j = 0; j < 4; j++) red[j * 256 + tid] = a[j][0] + a[j][1];
    __syncthreads();
    if (tid < 64) {
        #pragma unroll
        for (int j = 0; j < 4; j++) {
            float s = (red[j*256 + tid] + red[j*256 + tid + 64])
                    + (red[j*256 + tid + 128] + red[j*256 + tid + 192]);
            out[(cog*4+j)*NTOK + p] = fmaxf(s + bias[cog*4+j], 0.f);
        }
    }
}

// conv2: 256 threads = 64 pixels x 4 ci-groups (32 ci each), smem reduce
__global__ __launch_bounds__(256) void conv2_kernel(
    const float* __restrict__ c1, const float* __restrict__ wt,
    const float* __restrict__ bias, float* __restrict__ gp)
{
    __shared__ float ws[1152];
    __shared__ float red[256];
    int co = blockIdx.x;
    int tid = threadIdx.x;
    int px = tid & 63, cig = tid >> 6;
    int p = blockIdx.y * 64 + px;
    for (int i = tid; i < 1152; i += 256) ws[i] = wt[co * 1152 + i];
    __syncthreads();
    int y = p / HW, x = p % HW;
    float a0 = 0.f, a1 = 0.f;
    for (int ci = cig * 32; ci < cig * 32 + 32; ci += 2) {
        #pragma unroll
        for (int dy = 0; dy < 3; dy++) {
            int yy = y + dy - 1; if ((unsigned)yy >= HW) continue;
            #pragma unroll
            for (int dx = 0; dx < 3; dx++) {
                int xx = x + dx - 1; if ((unsigned)xx >= HW) continue;
                int po = yy * HW + xx, wi = dy * 3 + dx;
                a0 = fmaf(c1[(ci+0) * NTOK + po], ws[(ci+0) * 9 + wi], a0);
                a1 = fmaf(c1[(ci+1) * NTOK + po], ws[(ci+1) * 9 + wi], a1);
            }
        }
    }
    red[tid] = a0 + a1;
    __syncthreads();
    if (tid < 64) {
        float a = bias[co] + (red[tid] + red[tid + 64]) + (red[tid + 128] + red[tid + 192]);
        gp[co * NTOK + p] = 1.0f / (1.0f + __expf(-a));
    }
}

__global__ __launch_bounds__(256) void sq_kernel(const float* __restrict__ x,
                                                 float* __restrict__ sq)
{
    int row = blockIdx.x * 8 + (threadIdx.x >> 5);
    int lane = threadIdx.x & 31;
    const float* r = x + row * CDIM;
    float s = 0.f;
    #pragma unroll
    for (int i = 0; i < 8; i++) { float v = r[lane + i * 32]; s = fmaf(v, v, s); }
    #pragma unroll
    for (int o = 16; o; o >>= 1) s += __shfl_xor_sync(0xffffffffu, s, o);
    if (lane == 0) sq[row] = s;
}

__global__ __launch_bounds__(256) void d2_tf32_kernel(
    const float* __restrict__ X, const float* __restrict__ sqv,
    float* __restrict__ C)
{
    __shared__ float As[128 * 36];
    __shared__ float Bs[128 * 36];
    const int tid = threadIdx.x;
    const int wid = tid >> 5, lane = tid & 31;
    const int warpM = wid >> 2, warpN = wid & 3;
    const int i0 = blockIdx.x * 128, j0 = blockIdx.y * 128;
    const int gid = lane >> 2, qid = lane & 3;

    float acc[4][4][4];
    #pragma unroll
    for (int a = 0; a < 4; a++)
        #pragma unroll
        for (int b = 0; b < 4; b++)
            #pragma unroll
            for (int c = 0; c < 4; c++) acc[a][b][c] = 0.f;

    const int lrow = tid >> 1;
    const int lk = (tid & 1) * 16;
    const float* Ag = X + (size_t)(i0 + lrow) * CDIM + lk;
    const float* Bg = X + (size_t)(j0 + lrow) * CDIM + lk;
    float* Asw = As + lrow * 36 + lk;
    float* Bsw = Bs + lrow * 36 + lk;

    for (int k0 = 0; k0 < CDIM; k0 += 32) {
        __syncthreads();
        #pragma unroll
        for (int q = 0; q < 4; q++) {
            float4 av = *(const float4*)(Ag + k0 + q * 4);
            float4 bv = *(const float4*)(Bg + k0 + q * 4);
            float4 at, bt;
            at.x = __uint_as_float(f2tf32(av.x)); at.y = __uint_as_float(f2tf32(av.y));
            at.z = __uint_as_float(f2tf32(av.z)); at.w = __uint_as_float(f2tf32(av.w));
            bt.x = __uint_as_float(f2tf32(bv.x)); bt.y = __uint_as_float(f2tf32(bv.y));
            bt.z = __uint_as_float(f2tf32(bv.z)); bt.w = __uint_as_float(f2tf32(bv.w));
            *(float4*)&Asw[q * 4] = at;
            *(float4*)&Bsw[q * 4] = bt;
        }
        __syncthreads();
        #pragma unroll
        for (int k8 = 0; k8 < 4; k8++) {
            unsigned af[4][4], bf[4][2];
            #pragma unroll
            for (int tm = 0; tm < 4; tm++) {
                const float* p = As + (warpM * 64 + tm * 16 + gid) * 36 + k8 * 8 + qid;
                af[tm][0] = __float_as_uint(p[0]);
                af[tm][1] = __float_as_uint(p[8 * 36]);
                af[tm][2] = __float_as_uint(p[4]);
                af[tm][3] = __float_as_uint(p[8 * 36 + 4]);
            }
            #pragma unroll
            for (int tn = 0; tn < 4; tn++) {
                const float* p = Bs + (warpN * 32 + tn * 8 + gid) * 36 + k8 * 8 + qid;
                bf[tn][0] = __float_as_uint(p[0]);
                bf[tn][1] = __float_as_uint(p[4]);
            }
            #pragma unroll
            for (int tm = 0; tm < 4; tm++)
                #pragma unroll
                for (int tn = 0; tn < 4; tn++)
                    mma_tf32(acc[tm][tn], af[tm][0], af[tm][1], af[tm][2], af[tm][3],
                             bf[tn][0], bf[tn][1]);
        }
    }

    #pragma unroll
    for (int tm = 0; tm < 4; tm++) {
        const int r0 = i0 + warpM * 64 + tm * 16 + gid;
        const float sr0 = sqv[r0], sr1 = sqv[r0 + 8];
        #pragma unroll
        for (int tn = 0; tn < 4; tn++) {
            const int c0i = j0 + warpN * 32 + tn * 8 + qid * 2;
            const float sc0 = sqv[c0i], sc1 = sqv[c0i + 1];
            float2 v0, v1;
            v0.x = sr0 + sc0 - 2.f * acc[tm][tn][0];
            v0.y = sr0 + sc1 - 2.f * acc[tm][tn][1];
            v1.x = sr1 + sc0 - 2.f * acc[tm][tn][2];
            v1.y = sr1 + sc1 - 2.f * acc[tm][tn][3];
            *(float2*)&C[(size_t)r0 * NPAD + c0i] = v0;
            *(float2*)&C[(size_t)(r0 + 8) * NPAD + c0i] = v1;
        }
    }
}

// single-pass tf32 GEMM: C = A.B^T + bias (EPI1: relu). 64x64 tile, 4 warps.
template<int EPI>
__global__ __launch_bounds__(128) void mma1_gemm(
    const float* __restrict__ A, const float* __restrict__ B,
    const float* __restrict__ bias, float* __restrict__ C,
    int Nn, int K)
{
    __shared__ float Ah[64 * 36], Bh[64 * 36];
    const int tid = threadIdx.x;
    const int wid = tid >> 5, lane = tid & 31;
    const int warpM = wid >> 1, warpN = wid & 1;
    const int i0 = blockIdx.x * 64, j0 = blockIdx.y * 64;
    const int gid = lane >> 2, qid = lane & 3;

    float acc[2][4][4];
    #pragma unroll
    for (int a = 0; a < 2; a++)
        #pragma unroll
        for (int b = 0; b < 4; b++)
            #pragma unroll
            for (int c = 0; c < 4; c++) acc[a][b][c] = 0.f;

    const int lrow = tid >> 1;
    const int lk = (tid & 1) * 16;
    const float* Ag = A + (size_t)(i0 + lrow) * K + lk;
    const float* Bg = B + (size_t)(j0 + lrow) * K + lk;
    const int sbase = lrow * 36 + lk;

    for (int k0 = 0; k0 < K; k0 += 32) {
        __syncthreads();
        #pragma unroll
        for (int q = 0; q < 4; q++) {
            float4 av = *(const float4*)(Ag + k0 + q * 4);
            float4 bv = *(const float4*)(Bg + k0 + q * 4);
            float4 at, bt;
            at.x = __uint_as_float(f2tf32(av.x)); at.y = __uint_as_float(f2tf32(av.y));
            at.z = __uint_as_float(f2tf32(av.z)); at.w = __uint_as_float(f2tf32(av.w));
            bt.x = __uint_as_float(f2tf32(bv.x)); bt.y = __uint_as_float(f2tf32(bv.y));
            bt.z = __uint_as_float(f2tf32(bv.z)); bt.w = __uint_as_float(f2tf32(bv.w));
            *(float4*)&Ah[sbase + q * 4] = at;
            *(float4*)&Bh[sbase + q * 4] = bt;
        }
        __syncthreads();
        #pragma unroll
        for (int k8 = 0; k8 < 4; k8++) {
            unsigned af[2][4], bf[4][2];
            #pragma unroll
            for (int tm = 0; tm < 2; tm++) {
                const int off = (warpM * 32 + tm * 16 + gid) * 36 + k8 * 8 + qid;
                af[tm][0] = __float_as_uint(Ah[off]);
                af[tm][1] = __float_as_uint(Ah[off + 8 * 36]);
                af[tm][2] = __float_as_uint(Ah[off + 4]);
                af[tm][3] = __float_as_uint(Ah[off + 8 * 36 + 4]);
            }
            #pragma unroll
            for (int tn = 0; tn < 4; tn++) {
                const int off = (warpN * 32 + tn * 8 + gid) * 36 + k8 * 8 + qid;
                bf[tn][0] = __float_as_uint(Bh[off]);
                bf[tn][1] = __float_as_uint(Bh[off + 4]);
            }
            #pragma unroll
            for (int tm = 0; tm < 2; tm++)
                #pragma unroll
                for (int tn = 0; tn < 4; tn++)
                    mma_tf32(acc[tm][tn], af[tm][0], af[tm][1], af[tm][2], af[tm][3],
                             bf[tn][0], bf[tn][1]);
        }
    }

    #pragma unroll
    for (int tm = 0; tm < 2; tm++) {
        const int r0 = i0 + warpM * 32 + tm * 16 + gid;
        #pragma unroll
        for (int tn = 0; tn < 4; tn++) {
            const int c0i = j0 + warpN * 32 + tn * 8 + qid * 2;
            const float b0 = bias[c0i], b1 = bias[c0i + 1];
            float2 v0, v1;
            v0.x = acc[tm][tn][0] + b0; v0.y = acc[tm][tn][1] + b1;
            v1.x = acc[tm][tn][2] + b0; v1.y = acc[tm][tn][3] + b1;
            if (EPI == 1) {
                v0.x = fmaxf(v0.x, 0.f); v0.y = fmaxf(v0.y, 0.f);
                v1.x = fmaxf(v1.x, 0.f); v1.y = fmaxf(v1.y, 0.f);
            }
            *(float2*)&C[(size_t)r0 * Nn + c0i] = v0;
            *(float2*)&C[(size_t)(r0 + 8) * Nn + c0i] = v1;
        }
    }
}

__global__ void zero_kernel(int* __restrict__ nearp, int* __restrict__ maxn) {
    int i = blockIdx.x * 256 + threadIdx.x;
    if (i < NTOK) nearp[i] = 0;
    if (i == 0) *maxn = 0;
}

// top-16 smallest per row; shfl-based argmin (2 barriers/extraction instead of 8)
__global__ __launch_bounds__(256) void topk_kernel(const float* __restrict__ d2,
                                                   int* __restrict__ nearp)
{
    __shared__ float vals[NTOK];
    __shared__ float wv[8];
    __shared__ int   wi[8];
    int row = blockIdx.x, tid = threadIdx.x;
    int lane = tid & 31, w = tid >> 5;
    const float* rp = d2 + (size_t)row * NPAD;
    for (int i = tid; i < NTOK; i += 256) vals[i] = rp[i];
    __syncthreads();
    for (int it = 0; it < TOPKK; it++) {
        float bv = 3.0e38f; int bi = 0x7FFFFFFF;
        for (int i = tid; i < NTOK; i += 256) {
            float v = vals[i];
            if (v < bv) { bv = v; bi = i; }
        }
        #pragma unroll
        for (int o = 16; o; o >>= 1) {
            float ov = __shfl_xor_sync(0xffffffffu, bv, o);
            int   oi = __shfl_xor_sync(0xffffffffu, bi, o);
            if (ov < bv || (ov == bv && oi < bi)) { bv = ov; bi = oi; }
        }
        if (lane == 0) { wv[w] = bv; wi[w] = bi; }
        __syncthreads();
        if (tid == 0) {
            float fv = wv[0]; int fi = wi[0];
            #pragma unroll
            for (int j = 1; j < 8; j++) {
                if (wv[j] < fv || (wv[j] == fv && wi[j] < fi)) { fv = wv[j]; fi = wi[j]; }
            }
            atomicAdd(&nearp[fi], 1);
            vals[fi] = 3.0e38f;
        }
        __syncthreads();
    }
}

__global__ __launch_bounds__(256) void maxnear_kernel(const int* __restrict__ nearp,
                                                      int* __restrict__ out)
{
    __shared__ int sm[256];
    int tid = threadIdx.x;
    int m = 0;
    for (int i = tid; i < NTOK; i += 256) m = max(m, nearp[i]);
    sm[tid] = m;
    __syncthreads();
    for (int s = 128; s > 0; s >>= 1) {
        if (tid < s) sm[tid] = max(sm[tid], sm[tid+s]);
        __syncthreads();
    }
    if (tid == 0) *out = sm[0];
}

__global__ void qkin_kernel(const float* __restrict__ x, const int* __restrict__ nearp,
                            const int* __restrict__ maxn, const float* __restrict__ emb,
                            float* __restrict__ out)
{
    int t = blockIdx.x, c = threadIdx.x;
    float nf = (float)nearp[t], mf = (float)(*maxn);
    int ni = (int)((nf / mf) * 9.0f);
    if (ni > 9) ni = 9;
    out[t * CDIM + c] = x[t * CDIM + c] + emb[ni * CDIM + c];
}

// Flash attention on tf32 mma.sync (unchanged from round 10)
__global__ __launch_bounds__(128) void attn_kernel(
    const float* __restrict__ Q, const float* __restrict__ Km,
    const float* __restrict__ V, const float* __restrict__ gp,
    float* __restrict__ O)
{
    __shared__ float Qs[64 * 36];
    __shared__ float Ks[64 * 36];
    __shared__ float Vts[32 * 68];
    __shared__ float Ps[4 * 16 * 68];
    __shared__ float gks[64];

    const int h = blockIdx.y, qb = blockIdx.x, tid = threadIdx.x;
    const int w = tid >> 5, lane = tid & 31;
    const int gid = lane >> 2, qid = lane & 3;
    const float scale = 0.17677669529663687f;

    for (int idx = tid; idx < 64 * 32; idx += 128) {
        int i = idx >> 5, d = idx & 31;
        float qv = Q[(size_t)(qb * 64 + i) * CDIM + h * 32 + d] * scale;
        Qs[i * 36 + d] = __uint_as_float(f2tf32(qv));
    }
    const float gq0 = gp[h * NTOK + qb * 64 + w * 16 + gid];
    const float gq1 = gp[h * NTOK + qb * 64 + w * 16 + gid + 8];

    float oacc[4][4];
    #pragma unroll
    for (int dt = 0; dt < 4; dt++)
        #pragma unroll
        for (int c = 0; c < 4; c++) oacc[dt][c] = 0.f;
    float m0 = -1e30f, m1 = -1e30f, l0 = 0.f, l1 = 0.f;
    float* Pw = Ps + w * (16 * 68);

    for (int kt = 0; kt < 49; kt++) {
        __syncthreads();
        for (int idx = tid; idx < 64 * 32; idx += 128) {
            int j = idx >> 5, d = idx & 31;
            size_t gbase = (size_t)(kt * 64 + j) * CDIM + h * 32 + d;
            Ks[j * 36 + d] = __uint_as_float(f2tf32(Km[gbase]));
            Vts[d * 68 + j] = __uint_as_float(f2tf32(V[gbase]));
        }
        if (tid < 64) gks[tid] = gp[h * NTOK + kt * 64 + tid];
        __syncthreads();

        float sc[8][4];
        #pragma unroll
        for (int tn = 0; tn < 8; tn++)
            #pragma unroll
            for (int c = 0; c < 4; c++) sc[tn][c] = 0.f;
        #pragma unroll
        for (int k8 = 0; k8 < 4; k8++) {
            const int aoff = (w * 16 + gid) * 36 + k8 * 8 + qid;
            unsigned a0 = __float_as_uint(Qs[aoff]);
            unsigned a1 = __float_as_uint(Qs[aoff + 8 * 36]);
            unsigned a2 = __float_as_uint(Qs[aoff + 4]);
            unsigned a3 = __float_as_uint(Qs[aoff + 8 * 36 + 4]);
            #pragma unroll
            for (int tn = 0; tn < 8; tn++) {
                const int boff = (tn * 8 + gid) * 36 + k8 * 8 + qid;
                mma_tf32(sc[tn], a0, a1, a2, a3,
                         __float_as_uint(Ks[boff]), __float_as_uint(Ks[boff + 4]));
            }
        }
        float mn0 = -1e30f, mn1 = -1e30f;
        #pragma unroll
        for (int tn = 0; tn < 8; tn++) {
            float ga = gks[tn * 8 + qid * 2], gb = gks[tn * 8 + qid * 2 + 1];
            sc[tn][0] += fabsf(gq0 - ga); sc[tn][1] += fabsf(gq0 - gb);
            sc[tn][2] += fabsf(gq1 - ga); sc[tn][3] += fabsf(gq1 - gb);
            mn0 = fmaxf(mn0, fmaxf(sc[tn][0], sc[tn][1]));
            mn1 = fmaxf(mn1, fmaxf(sc[tn][2], sc[tn][3]));
        }
        mn0 = fmaxf(mn0, __shfl_xor_sync(0xffffffffu, mn0, 1));
        mn0 = fmaxf(mn0, __shfl_xor_sync(0xffffffffu, mn0, 2));
        mn1 = fmaxf(mn1, __shfl_xor_sync(0xffffffffu, mn1, 1));
        mn1 = fmaxf(mn1, __shfl_xor_sync(0xffffffffu, mn1, 2));
        if (mn0 > m0) {
            float corr = fexp(m0 - mn0);
            l0 *= corr;
            #pragma unroll
            for (int dt = 0; dt < 4; dt++) { oacc[dt][0] *= corr; oacc[dt][1] *= corr; }
            m0 = mn0;
        }
        if (mn1 > m1) {
            float corr = fexp(m1 - mn1);
            l1 *= corr;
            #pragma unroll
            for (int dt = 0; dt < 4; dt++) { oacc[dt][2] *= corr; oacc[dt][3] *= corr; }
            m1 = mn1;
        }
        float ps0 = 0.f, ps1 = 0.f;
        #pragma unroll
        for (int tn = 0; tn < 8; tn++) {
            float p00 = fexp(sc[tn][0] - m0), p01 = fexp(sc[tn][1] - m0);
            float p10 = fexp(sc[tn][2] - m1), p11 = fexp(sc[tn][3] - m1);
            ps0 += p00 + p01; ps1 += p10 + p11;
            int col = tn * 8 + qid * 2;
            Pw[gid * 68 + col]       = __uint_as_float(f2tf32(p00));
            Pw[gid * 68 + col + 1]   = __uint_as_float(f2tf32(p01));
            Pw[(gid + 8) * 68 + col]     = __uint_as_float(f2tf32(p10));
            Pw[(gid + 8) * 68 + col + 1] = __uint_as_float(f2tf32(p11));
        }
        ps0 += __shfl_xor_sync(0xffffffffu, ps0, 1);
        ps0 += __shfl_xor_sync(0xffffffffu, ps0, 2);
        ps1 += __shfl_xor_sync(0xffffffffu, ps1, 1);
        ps1 += __shfl_xor_sync(0xffffffffu, ps1, 2);
        l0 += ps0; l1 += ps1;
        __syncwarp();
        #pragma unroll
        for (int k8 = 0; k8 < 8; k8++) {
            const int aoff = gid * 68 + k8 * 8 + qid;
            unsigned a0 = __float_as_uint(Pw[aoff]);
            unsigned a1 = __float_as_uint(Pw[aoff + 8 * 68]);
            unsigned a2 = __float_as_uint(Pw[aoff + 4]);
            unsigned a3 = __float_as_uint(Pw[aoff + 8 * 68 + 4]);
            #pragma unroll
            for (int dt = 0; dt < 4; dt++) {
                const int boff = (dt * 8 + gid) * 68 + k8 * 8 + qid;
                mma_tf32(oacc[dt], a0, a1, a2, a3,
                         __float_as_uint(Vts[boff]), __float_as_uint(Vts[boff + 4]));
            }
        }
        __syncwarp();
    }

    const float inv0 = 1.f / l0, inv1 = 1.f / l1;
    const int r0g = qb * 64 + w * 16 + gid, r1g = r0g + 8;
    #pragma unroll
    for (int dt = 0; dt < 4; dt++) {
        const int col = h * 32 + dt * 8 + qid * 2;
        float2 v0, v1;
        v0.x = oacc[dt][0] * inv0; v0.y = oacc[dt][1] * inv0;
        v1.x = oacc[dt][2] * inv1; v1.y = oacc[dt][3] * inv1;
        *(float2*)&O[(size_t)r0g * CDIM + col] = v0;
        *(float2*)&O[(size_t)r1g * CDIM + col] = v1;
    }
}

template<int FINAL>
__global__ __launch_bounds__(256) void add_ln_kernel(
    const float* __restrict__ a, const float* __restrict__ b,
    const float* __restrict__ g, const float* __restrict__ be,
    float* __restrict__ out)
{
    __shared__ float red[8];
    int row = blockIdx.x, tid = threadIdx.x;
    float v = a[row * CDIM + tid];
    if (!FINAL) v += b[row * CDIM + tid];
    float s = v;
    #pragma unroll
    for (int o = 16; o; o >>= 1) s += __shfl_xor_sync(0xffffffffu, s, o);
    if ((tid & 31) == 0) red[tid >> 5] = s;
    __syncthreads();
    float mean = 0.f;
    #pragma unroll
    for (int i = 0; i < 8; i++) mean += red[i];
    mean *= (1.f / 256.f);
    float d = v - mean;
    __syncthreads();
    s = d * d;
    #pragma unroll
    for (int o = 16; o; o >>= 1) s += __shfl_xor_sync(0xffffffffu, s, o);
    if ((tid & 31) == 0) red[tid >> 5] = s;
    __syncthreads();
    float var = 0.f;
    #pragma unroll
    for (int i = 0; i < 8; i++) var += red[i];
    var *= (1.f / 256.f);
    float r = d * rsqrtf(var + 1e-5f) * g[tid] + be[tid];
    if (FINAL) out[tid * NTOK + row] = r;
    else       out[row * CDIM + tid] = r;
}

extern "C" void kernel_launch(void* const* d_in, const int* in_sizes, int n_in,
                              void* d_out, int out_size)
{
    (void)in_sizes; (void)n_in; (void)out_size;
    const float* src  = (const float*)d_in[0];
    const float* c1w  = (const float*)d_in[1];
    const float* c1b  = (const float*)d_in[2];
    const float* c2w  = (const float*)d_in[3];
    const float* c2b  = (const float*)d_in[4];
    const float* nemb = (const float*)d_in[5];
    const float* Wq   = (const float*)d_in[6];
    const float* bq   = (const float*)d_in[7];
    const float* Wk   = (const float*)d_in[8];
    const float* bk   = (const float*)d_in[9];
    const float* Wv   = (const float*)d_in[10];
    const float* bv   = (const float*)d_in[11];
    const float* Wo   = (const float*)d_in[12];
    const float* bo   = (const float*)d_in[13];
    const float* W1   = (const float*)d_in[14];
    const float* b1   = (const float*)d_in[15];
    const float* W2   = (const float*)d_in[16];
    const float* b2   = (const float*)d_in[17];
    const float* ln1g = (const float*)d_in[18];
    const float* ln1b = (const float*)d_in[19];
    const float* ln2g = (const float*)d_in[20];
    const float* ln2b = (const float*)d_in[21];
    const float* ng   = (const float*)d_in[22];
    const float* nb   = (const float*)d_in[23];

    float *c1, *gp, *x, *sqv, *d2, *qkin, *q, *k, *v, *att, *ffh, *yb;
    int *nearp, *maxn;
    cudaGetSymbolAddress((void**)&c1,    g_c1);
    cudaGetSymbolAddress((void**)&gp,    g_gp);
    cudaGetSymbolAddress((void**)&x,     g_x);
    cudaGetSymbolAddress((void**)&sqv,   g_sq);
    cudaGetSymbolAddress((void**)&d2,    g_d2);
    cudaGetSymbolAddress((void**)&nearp, g_near);
    cudaGetSymbolAddress((void**)&maxn,  g_maxnear);
    cudaGetSymbolAddress((void**)&qkin,  g_qkin);
    cudaGetSymbolAddress((void**)&q,     g_q);
    cudaGetSymbolAddress((void**)&k,     g_k);
    cudaGetSymbolAddress((void**)&v,     g_v);
    cudaGetSymbolAddress((void**)&att,   g_att);
    cudaGetSymbolAddress((void**)&ffh,   g_ffh);
    cudaGetSymbolAddress((void**)&yb,    g_y);

    pad_kernel<<<64, 256>>>(x, sqv);
    transpose_kernel<<<dim3(98, 8), dim3(32, 32)>>>(src, x);
    conv1_kernel<<<dim3(32, 49), 256>>>(src, c1w, c1b, c1);
    conv2_kernel<<<dim3(8, 49), 256>>>(c1, c2w, c2b, gp);

    for (int i = 0; i < NLAYER; i++) {
        sq_kernel<<<392, 256>>>(x, sqv);
        d2_tf32_kernel<<<dim3(25, 25), 256>>>(x, sqv, d2);
        zero_kernel<<<13, 256>>>(nearp, maxn);
        topk_kernel<<<NTOK, 256>>>(d2, nearp);
        maxnear_kernel<<<1, 256>>>(nearp, maxn);
        qkin_kernel<<<NTOK, 256>>>(x, nearp, maxn, nemb, qkin);

        mma1_gemm<0><<<dim3(50, 4), 128>>>(qkin, Wq + i*CDIM*CDIM, bq + i*CDIM, q, CDIM, CDIM);
        mma1_gemm<0><<<dim3(50, 4), 128>>>(qkin, Wk + i*CDIM*CDIM, bk + i*CDIM, k, CDIM, CDIM);
        mma1_gemm<0><<<dim3(50, 4), 128>>>(x,    Wv + i*CDIM*CDIM, bv + i*CDIM, v, CDIM, CDIM);

        attn_kernel<<<dim3(49, NHEAD), 128>>>(q, k, v, gp, att);

        mma1_gemm<0><<<dim3(50, 4), 128>>>(att, Wo + i*CDIM*CDIM, bo + i*CDIM, yb, CDIM, CDIM);
        add_ln_kernel<0><<<NTOK, 256>>>(x, yb, ln1g + i*CDIM, ln1b + i*CDIM, x);

        mma1_gemm<1><<<dim3(50, 16), 128>>>(x, W1 + i*DFFN*CDIM, b1 + i*DFFN, ffh, DFFN, CDIM);
        mma1_gemm<0><<<dim3(50, 4), 128>>>(ffh, W2 + i*CDIM*DFFN, b2 + i*CDIM, yb, CDIM, DFFN);
        add_ln_kernel<0><<<NTOK, 256>>>(x, yb, ln2g + i*CDIM, ln2b + i*CDIM, x);
    }

    add_ln_kernel<1><<<NTOK, 256>>>(x, nullptr, ng, nb, (float*)d_out);
}